// round 1
// baseline (speedup 1.0000x reference)
#include <cuda_runtime.h>

// Problem constants
constexpr int SEQ = 2048;   // L
constexpr int EMB = 1024;   // E
constexpr int NH  = 16;     // heads
constexpr int HD  = 64;     // head dim

// Scratch (allocation-free rule: __device__ globals)
__device__ float g_q[SEQ * EMB];
__device__ float g_k[SEQ * EMB];
__device__ float g_v[SEQ * EMB];
__device__ float g_ctx[SEQ * EMB];

// ---------------------------------------------------------------------------
// C[M,N] = A[M,K] @ B[N,K]^T (+ bias[N]) ; classic 128x128x16 SGEMM, 8x8 frags
// ---------------------------------------------------------------------------
__global__ void __launch_bounds__(256) gemm_nt(const float* __restrict__ A,
                                               const float* __restrict__ B,
                                               const float* __restrict__ bias,
                                               float* __restrict__ C,
                                               int M, int N, int K)
{
    constexpr int BK = 16;
    __shared__ float As[BK][132];   // transposed [k][m], pad 4 keeps 16B align
    __shared__ float Bs[BK][132];   // transposed [k][n]

    const int tid = threadIdx.x;
    const int tx  = tid & 15;       // n-tile lane
    const int ty  = tid >> 4;       // m-tile lane
    const int m0  = blockIdx.y * 128;
    const int n0  = blockIdx.x * 128;

    float acc[8][8];
#pragma unroll
    for (int i = 0; i < 8; i++)
#pragma unroll
        for (int j = 0; j < 8; j++) acc[i][j] = 0.f;

    for (int k0 = 0; k0 < K; k0 += BK) {
#pragma unroll
        for (int p = 0; p < 2; p++) {
            int f   = tid + p * 256;      // 512 float4 per tile
            int row = f >> 2;             // 0..127
            int c4  = (f & 3) * 4;        // 0,4,8,12
            float4 va = *(const float4*)&A[(size_t)(m0 + row) * K + k0 + c4];
            As[c4 + 0][row] = va.x; As[c4 + 1][row] = va.y;
            As[c4 + 2][row] = va.z; As[c4 + 3][row] = va.w;
            float4 vb = *(const float4*)&B[(size_t)(n0 + row) * K + k0 + c4];
            Bs[c4 + 0][row] = vb.x; Bs[c4 + 1][row] = vb.y;
            Bs[c4 + 2][row] = vb.z; Bs[c4 + 3][row] = vb.w;
        }
        __syncthreads();

#pragma unroll
        for (int k = 0; k < BK; k++) {
            float a[8], b[8];
            *(float4*)&a[0] = *(const float4*)&As[k][ty * 4];
            *(float4*)&a[4] = *(const float4*)&As[k][64 + ty * 4];
            *(float4*)&b[0] = *(const float4*)&Bs[k][tx * 4];
            *(float4*)&b[4] = *(const float4*)&Bs[k][64 + tx * 4];
#pragma unroll
            for (int i = 0; i < 8; i++)
#pragma unroll
                for (int j = 0; j < 8; j++)
                    acc[i][j] = fmaf(a[i], b[j], acc[i][j]);
        }
        __syncthreads();
    }

#pragma unroll
    for (int i = 0; i < 8; i++) {
        int gm = m0 + ((i < 4) ? ty * 4 + i : 64 + ty * 4 + (i - 4));
#pragma unroll
        for (int jj = 0; jj < 2; jj++) {
            int gn = n0 + ((jj == 0) ? tx * 4 : 64 + tx * 4);
            float4 o;
            o.x = acc[i][jj * 4 + 0];
            o.y = acc[i][jj * 4 + 1];
            o.z = acc[i][jj * 4 + 2];
            o.w = acc[i][jj * 4 + 3];
            if (bias) {
                o.x += bias[gn + 0]; o.y += bias[gn + 1];
                o.z += bias[gn + 2]; o.w += bias[gn + 3];
            }
            *(float4*)&C[(size_t)gm * N + gn] = o;
        }
    }
}

// ---------------------------------------------------------------------------
// Flash attention, fp32. One block = 64 queries of one head, 256 threads.
// Online softmax over 32 key tiles of 64.
//   energy = q.k + bias(dist);  p = softmax(energy / 32);  ctx = p @ v
// Shared: QsT/KsT/PsT [64][68] (transposed, padded), Vs [64][64], row stats.
// ---------------------------------------------------------------------------
constexpr int FL_STRIDE = 68;    // 64 + 4 pad, keeps float4 alignment
constexpr int FLASH_SMEM = (3 * 64 * FL_STRIDE + 64 * 64 + 3 * 64) * 4; // 69376 B

__global__ void __launch_bounds__(256) flash_attn(const float* __restrict__ Qm,
                                                  const float* __restrict__ Km,
                                                  const float* __restrict__ Vm,
                                                  const float* __restrict__ dist,
                                                  float* __restrict__ ctx)
{
    extern __shared__ float sm[];
    float* QsT  = sm;                          // [d][q]  64x68
    float* KsT  = sm + 64 * FL_STRIDE;         // [d][k]  64x68
    float* PsT  = sm + 2 * 64 * FL_STRIDE;     // [k][q]  64x68
    float* Vs   = sm + 3 * 64 * FL_STRIDE;     // [k][d]  64x64
    float* mrow = Vs + 64 * 64;                // [64]
    float* lrow = mrow + 64;                   // [64]
    float* rrow = lrow + 64;                   // [64]

    const int tid  = threadIdx.x;
    const int tx   = tid & 15;
    const int ty   = tid >> 4;
    const int q0   = blockIdx.x * 64;
    const int hoff = blockIdx.y * HD;

    // Load Q tile transposed: 64 rows x 16 float4
#pragma unroll
    for (int p = 0; p < 4; p++) {
        int f   = tid + p * 256;
        int row = f >> 4;
        int c4  = (f & 15) * 4;
        float4 v = *(const float4*)&Qm[(size_t)(q0 + row) * EMB + hoff + c4];
        QsT[(c4 + 0) * FL_STRIDE + row] = v.x;
        QsT[(c4 + 1) * FL_STRIDE + row] = v.y;
        QsT[(c4 + 2) * FL_STRIDE + row] = v.z;
        QsT[(c4 + 3) * FL_STRIDE + row] = v.w;
    }
    if (tid < 64) { mrow[tid] = -1e30f; lrow[tid] = 0.f; }

    float acc[4][4];
#pragma unroll
    for (int i = 0; i < 4; i++)
#pragma unroll
        for (int j = 0; j < 4; j++) acc[i][j] = 0.f;

    for (int kt = 0; kt < SEQ / 64; kt++) {
        const int kb = kt * 64;

        // Load K tile (transposed) + V tile (natural)
#pragma unroll
        for (int p = 0; p < 4; p++) {
            int f   = tid + p * 256;
            int row = f >> 4;
            int c4  = (f & 15) * 4;
            float4 kv = *(const float4*)&Km[(size_t)(kb + row) * EMB + hoff + c4];
            KsT[(c4 + 0) * FL_STRIDE + row] = kv.x;
            KsT[(c4 + 1) * FL_STRIDE + row] = kv.y;
            KsT[(c4 + 2) * FL_STRIDE + row] = kv.z;
            KsT[(c4 + 3) * FL_STRIDE + row] = kv.w;
            float4 vv = *(const float4*)&Vm[(size_t)(kb + row) * EMB + hoff + c4];
            *(float4*)&Vs[row * 64 + c4] = vv;
        }
        __syncthreads();

        // S = Q @ K^T (4x4 per thread over 16x16 thread grid)
        float s[4][4];
#pragma unroll
        for (int i = 0; i < 4; i++)
#pragma unroll
            for (int j = 0; j < 4; j++) s[i][j] = 0.f;
#pragma unroll
        for (int d = 0; d < 64; d++) {
            float a[4], b[4];
            *(float4*)a = *(const float4*)&QsT[d * FL_STRIDE + ty * 4];
            *(float4*)b = *(const float4*)&KsT[d * FL_STRIDE + tx * 4];
#pragma unroll
            for (int i = 0; i < 4; i++)
#pragma unroll
                for (int j = 0; j < 4; j++)
                    s[i][j] = fmaf(a[i], b[j], s[i][j]);
        }

        // Add distance bias, scale by 1/sqrt(E)=1/32, store transposed [k][q]
        const float sc = 0.03125f;
#pragma unroll
        for (int i = 0; i < 4; i++) {
            int qg = q0 + ty * 4 + i;
            float4 dm = *(const float4*)&dist[(size_t)qg * SEQ + kb + tx * 4];
            float b0 = (dm.x == 0.f) ? 0.f : 1.f / (dm.x + 1.f);
            float b1 = (dm.y == 0.f) ? 0.f : 1.f / (dm.y + 1.f);
            float b2 = (dm.z == 0.f) ? 0.f : 1.f / (dm.z + 1.f);
            float b3 = (dm.w == 0.f) ? 0.f : 1.f / (dm.w + 1.f);
            PsT[(tx * 4 + 0) * FL_STRIDE + ty * 4 + i] = (s[i][0] + b0) * sc;
            PsT[(tx * 4 + 1) * FL_STRIDE + ty * 4 + i] = (s[i][1] + b1) * sc;
            PsT[(tx * 4 + 2) * FL_STRIDE + ty * 4 + i] = (s[i][2] + b2) * sc;
            PsT[(tx * 4 + 3) * FL_STRIDE + ty * 4 + i] = (s[i][3] + b3) * sc;
        }
        __syncthreads();

        // Online softmax: 4 lanes per row, 16 keys each
        {
            const int q   = tid >> 2;
            const int seg = tid & 3;
            float mx = -1e30f;
#pragma unroll
            for (int t = 0; t < 16; t++)
                mx = fmaxf(mx, PsT[(seg * 16 + t) * FL_STRIDE + q]);
            mx = fmaxf(mx, __shfl_xor_sync(0xffffffffu, mx, 1));
            mx = fmaxf(mx, __shfl_xor_sync(0xffffffffu, mx, 2));
            float mold = mrow[q];
            float mnew = fmaxf(mold, mx);
            float sum = 0.f;
#pragma unroll
            for (int t = 0; t < 16; t++) {
                int idx = (seg * 16 + t) * FL_STRIDE + q;
                float e = __expf(PsT[idx] - mnew);
                PsT[idx] = e;
                sum += e;
            }
            sum += __shfl_xor_sync(0xffffffffu, sum, 1);
            sum += __shfl_xor_sync(0xffffffffu, sum, 2);
            if (seg == 0) {
                float fr = __expf(mold - mnew);
                rrow[q] = fr;
                lrow[q] = lrow[q] * fr + sum;
                mrow[q] = mnew;
            }
        }
        __syncthreads();

        // Rescale accumulator and accumulate P @ V
        {
            float r[4];
#pragma unroll
            for (int i = 0; i < 4; i++) r[i] = rrow[ty * 4 + i];
#pragma unroll
            for (int i = 0; i < 4; i++)
#pragma unroll
                for (int j = 0; j < 4; j++) acc[i][j] *= r[i];
#pragma unroll
            for (int k = 0; k < 64; k++) {
                float p[4], v[4];
                *(float4*)p = *(const float4*)&PsT[k * FL_STRIDE + ty * 4];
                *(float4*)v = *(const float4*)&Vs[k * 64 + tx * 4];
#pragma unroll
                for (int i = 0; i < 4; i++)
#pragma unroll
                    for (int j = 0; j < 4; j++)
                        acc[i][j] = fmaf(p[i], v[j], acc[i][j]);
            }
        }
        __syncthreads();
    }

    // Normalize and write context
#pragma unroll
    for (int i = 0; i < 4; i++) {
        float inv = 1.f / lrow[ty * 4 + i];
        float4 o;
        o.x = acc[i][0] * inv; o.y = acc[i][1] * inv;
        o.z = acc[i][2] * inv; o.w = acc[i][3] * inv;
        *(float4*)&ctx[(size_t)(q0 + ty * 4 + i) * EMB + hoff + tx * 4] = o;
    }
}

// ---------------------------------------------------------------------------
extern "C" void kernel_launch(void* const* d_in, const int* in_sizes, int n_in,
                              void* d_out, int out_size)
{
    const float* values = (const float*)d_in[0];
    const float* keys   = (const float*)d_in[1];
    const float* query  = (const float*)d_in[2];
    const float* dist   = (const float*)d_in[3];
    const float* Wv     = (const float*)d_in[4];
    const float* Wk     = (const float*)d_in[5];
    const float* Wq     = (const float*)d_in[6];
    const float* Wo     = (const float*)d_in[7];
    const float* bo     = (const float*)d_in[8];
    float* out = (float*)d_out;

    float *qb, *kb, *vb, *cb;
    cudaGetSymbolAddress((void**)&qb, g_q);
    cudaGetSymbolAddress((void**)&kb, g_k);
    cudaGetSymbolAddress((void**)&vb, g_v);
    cudaGetSymbolAddress((void**)&cb, g_ctx);

    cudaFuncSetAttribute(flash_attn,
                         cudaFuncAttributeMaxDynamicSharedMemorySize, FLASH_SMEM);

    dim3 gproj(EMB / 128, SEQ / 128);   // (8, 16)
    gemm_nt<<<gproj, 256>>>(query,  Wq, nullptr, qb, SEQ, EMB, EMB);
    gemm_nt<<<gproj, 256>>>(keys,   Wk, nullptr, kb, SEQ, EMB, EMB);
    gemm_nt<<<gproj, 256>>>(values, Wv, nullptr, vb, SEQ, EMB, EMB);

    flash_attn<<<dim3(SEQ / 64, NH), 256, FLASH_SMEM>>>(qb, kb, vb, dist, cb);

    gemm_nt<<<gproj, 256>>>(cb, Wo, bo, out, SEQ, EMB, EMB);
}

// round 3
// speedup vs baseline: 2.9943x; 2.9943x over previous
#include <cuda_runtime.h>
#include <cuda_bf16.h>
#include <cstdint>

// ---------------- problem constants ----------------
constexpr int L  = 2048;
constexpr int E  = 1024;
constexpr int NH = 16;
constexpr int HD = 64;

// ---------------- device scratch ----------------
__device__ __nv_bfloat16 g_xqh[L * E], g_xql[L * E];
__device__ __nv_bfloat16 g_xkh[L * E], g_xkl[L * E];
__device__ __nv_bfloat16 g_xvh[L * E], g_xvl[L * E];
__device__ __nv_bfloat16 g_wqh[E * E], g_wql[E * E];
__device__ __nv_bfloat16 g_wkh[E * E], g_wkl[E * E];
__device__ __nv_bfloat16 g_wvh[E * E], g_wvl[E * E];
__device__ __nv_bfloat16 g_woh[E * E], g_wol[E * E];
__device__ __nv_bfloat16 g_pqh[L * E], g_pql[L * E];
__device__ __nv_bfloat16 g_pkh[L * E], g_pkl[L * E];
__device__ __nv_bfloat16 g_pvh[L * E], g_pvl[L * E];
__device__ __nv_bfloat16 g_cxh[L * E], g_cxl[L * E];
__device__ float g_bias[(size_t)L * L];

// ---------------- helpers ----------------
__device__ __forceinline__ uint32_t s2u(const void* p) {
    uint32_t a;
    asm("{ .reg .u64 t; cvta.to.shared.u64 t, %1; cvt.u32.u64 %0, t; }"
        : "=r"(a) : "l"(p));
    return a;
}

__device__ __forceinline__ uint32_t sw128(uint32_t off) {
    return off ^ ((off >> 3) & 0x70);
}

#define CP_ASYNC16(dst, src) \
    asm volatile("cp.async.cg.shared.global [%0], [%1], 16;" \
        :: "r"(dst), "l"(src))
#define CP_COMMIT() asm volatile("cp.async.commit_group;" ::: "memory")
#define CP_WAIT1()  asm volatile("cp.async.wait_group 1;" ::: "memory")
#define CP_WAIT0()  asm volatile("cp.async.wait_group 0;" ::: "memory")

#define LDSM4(r0, r1, r2, r3, a) \
    asm volatile("ldmatrix.sync.aligned.m8n8.x4.shared.b16 {%0,%1,%2,%3}, [%4];" \
        : "=r"(r0), "=r"(r1), "=r"(r2), "=r"(r3) : "r"(a))
#define LDSM4T(r0, r1, r2, r3, a) \
    asm volatile("ldmatrix.sync.aligned.m8n8.x4.trans.shared.b16 {%0,%1,%2,%3}, [%4];" \
        : "=r"(r0), "=r"(r1), "=r"(r2), "=r"(r3) : "r"(a))

#define MMA16816(d, a, b) \
    asm volatile("mma.sync.aligned.m16n8k16.row.col.f32.bf16.bf16.f32 " \
        "{%0,%1,%2,%3}, {%4,%5,%6,%7}, {%8,%9}, {%0,%1,%2,%3};" \
        : "+f"((d)[0]), "+f"((d)[1]), "+f"((d)[2]), "+f"((d)[3]) \
        : "r"((a)[0]), "r"((a)[1]), "r"((a)[2]), "r"((a)[3]), \
          "r"((b)[0]), "r"((b)[1]))

__device__ __forceinline__ void split2(float f0, float f1,
                                       uint32_t& hp, uint32_t& lp) {
    __nv_bfloat16 h0 = __float2bfloat16(f0), h1 = __float2bfloat16(f1);
    __nv_bfloat16 l0 = __float2bfloat16(f0 - __bfloat162float(h0));
    __nv_bfloat16 l1 = __float2bfloat16(f1 - __bfloat162float(h1));
    hp = ((uint32_t)__bfloat16_as_ushort(h1) << 16) | __bfloat16_as_ushort(h0);
    lp = ((uint32_t)__bfloat16_as_ushort(l1) << 16) | __bfloat16_as_ushort(l0);
}

// cp.async one [128 x 64] bf16 tile into SW128-swizzled smem (256 threads)
__device__ __forceinline__ void cp_tile(uint32_t dst, const __nv_bfloat16* src,
                                        int ld, int tid) {
#pragma unroll
    for (int i = 0; i < 4; i++) {
        int u   = i * 256 + tid;
        int row = u >> 3;
        int ch  = u & 7;
        uint32_t d = dst + sw128((uint32_t)(row * 128 + ch * 16));
        const void* s = src + (size_t)row * ld + ch * 8;
        CP_ASYNC16(d, s);
    }
}

// ---------------- fp32 -> (hi,lo) bf16 split ----------------
__global__ void convert_split(const float* __restrict__ x,
                              __nv_bfloat16* __restrict__ h,
                              __nv_bfloat16* __restrict__ l, int n)
{
    int i = (blockIdx.x * blockDim.x + threadIdx.x) * 4;
    if (i >= n) return;
    float4 v = *reinterpret_cast<const float4*>(x + i);
    uint32_t h0, l0, h1, l1;
    split2(v.x, v.y, h0, l0);
    split2(v.z, v.w, h1, l1);
    uint2 ph = {h0, h1}, pl = {l0, l1};
    *reinterpret_cast<uint2*>(h + i) = ph;
    *reinterpret_cast<uint2*>(l + i) = pl;
}

// ---------------- precompute distance bias ----------------
__global__ void bias_prep(const float* __restrict__ d, float* __restrict__ b, int n)
{
    int i = (blockIdx.x * blockDim.x + threadIdx.x) * 4;
    if (i >= n) return;
    float4 v = *reinterpret_cast<const float4*>(d + i);
    float4 o;
    o.x = (v.x == 0.f) ? 0.f : 1.f / (v.x + 1.f);
    o.y = (v.y == 0.f) ? 0.f : 1.f / (v.y + 1.f);
    o.z = (v.z == 0.f) ? 0.f : 1.f / (v.z + 1.f);
    o.w = (v.w == 0.f) ? 0.f : 1.f / (v.w + 1.f);
    *reinterpret_cast<float4*>(b + i) = o;
}

// ---------------- split-bf16 GEMM: C = A @ B^T via mma.sync ----------------
// 128x128 block, 8 warps (2x4), warp tile 64x32, K chunk 64, double buffered.
constexpr int GEMM_SMEM = 2 * 4 * 16384;    // 131072

template <int MODE>
__global__ void __launch_bounds__(256)
gemm_tc(const __nv_bfloat16* __restrict__ Ah, const __nv_bfloat16* __restrict__ Al,
        const __nv_bfloat16* __restrict__ Bh, const __nv_bfloat16* __restrict__ Bl,
        __nv_bfloat16* __restrict__ Ch, __nv_bfloat16* __restrict__ Cl,
        float* __restrict__ Cf, const float* __restrict__ bvec,
        int M, int N, int K)
{
    extern __shared__ char sm[];
    const uint32_t sb = s2u(sm);
    const int tid  = threadIdx.x;
    const int wid  = tid >> 5;
    const int lane = tid & 31;
    const int m0w  = (wid >> 2) * 64;
    const int n0w  = (wid & 3) * 32;
    const int m0 = blockIdx.y * 128;
    const int n0 = blockIdx.x * 128;
    const int sub = lane >> 3, lr = lane & 7;

    float acc[4][4][4];
#pragma unroll
    for (int i = 0; i < 4; i++)
#pragma unroll
        for (int j = 0; j < 4; j++)
#pragma unroll
            for (int k = 0; k < 4; k++) acc[i][j][k] = 0.f;

    const int NC = K / 64;

    // prologue: chunk 0
    {
        uint32_t base = sb;
        cp_tile(base,         Ah + (size_t)m0 * K, K, tid);
        cp_tile(base + 16384, Al + (size_t)m0 * K, K, tid);
        cp_tile(base + 32768, Bh + (size_t)n0 * K, K, tid);
        cp_tile(base + 49152, Bl + (size_t)n0 * K, K, tid);
        CP_COMMIT();
    }

    for (int kc = 0; kc < NC; kc++) {
        if (kc + 1 < NC) {
            uint32_t base = sb + ((kc + 1) & 1) * 65536;
            const int k0 = (kc + 1) * 64;
            cp_tile(base,         Ah + (size_t)m0 * K + k0, K, tid);
            cp_tile(base + 16384, Al + (size_t)m0 * K + k0, K, tid);
            cp_tile(base + 32768, Bh + (size_t)n0 * K + k0, K, tid);
            cp_tile(base + 49152, Bl + (size_t)n0 * K + k0, K, tid);
            CP_COMMIT();
            CP_WAIT1();
        } else {
            CP_WAIT0();
        }
        __syncthreads();

        const uint32_t base = sb + (kc & 1) * 65536;
#pragma unroll
        for (int ks = 0; ks < 4; ks++) {
            const int ch = ks * 2 + (sub >> 1);
            uint32_t ah[4][4], al[4][4], bh[4][2], bl[4][2];
#pragma unroll
            for (int mi = 0; mi < 4; mi++) {
                int r = m0w + mi * 16 + (sub & 1) * 8 + lr;
                uint32_t off = sw128((uint32_t)(r * 128 + ch * 16));
                LDSM4(ah[mi][0], ah[mi][1], ah[mi][2], ah[mi][3], base + off);
                LDSM4(al[mi][0], al[mi][1], al[mi][2], al[mi][3], base + 16384 + off);
            }
#pragma unroll
            for (int ng = 0; ng < 2; ng++) {
                int r = n0w + ng * 16 + (sub & 1) * 8 + lr;
                uint32_t off = sw128((uint32_t)(r * 128 + ch * 16));
                uint32_t t0, t1, t2, t3;
                LDSM4(t0, t1, t2, t3, base + 32768 + off);
                bh[2*ng][0] = t0; bh[2*ng][1] = t2;
                bh[2*ng+1][0] = t1; bh[2*ng+1][1] = t3;
                LDSM4(t0, t1, t2, t3, base + 49152 + off);
                bl[2*ng][0] = t0; bl[2*ng][1] = t2;
                bl[2*ng+1][0] = t1; bl[2*ng+1][1] = t3;
            }
#pragma unroll
            for (int mi = 0; mi < 4; mi++)
#pragma unroll
                for (int ni = 0; ni < 4; ni++) {
                    MMA16816(acc[mi][ni], ah[mi], bh[ni]);
                    MMA16816(acc[mi][ni], ah[mi], bl[ni]);
                    MMA16816(acc[mi][ni], al[mi], bh[ni]);
                }
        }
        __syncthreads();
    }

    // epilogue
#pragma unroll
    for (int mi = 0; mi < 4; mi++) {
        int r1 = m0 + m0w + mi * 16 + (lane >> 2);
        int r2 = r1 + 8;
#pragma unroll
        for (int ni = 0; ni < 4; ni++) {
            int col = n0 + n0w + ni * 8 + (lane & 3) * 2;
            float* d = acc[mi][ni];
            if (MODE == 0) {
                uint32_t hp, lp;
                split2(d[0], d[1], hp, lp);
                *reinterpret_cast<uint32_t*>(Ch + (size_t)r1 * N + col) = hp;
                *reinterpret_cast<uint32_t*>(Cl + (size_t)r1 * N + col) = lp;
                split2(d[2], d[3], hp, lp);
                *reinterpret_cast<uint32_t*>(Ch + (size_t)r2 * N + col) = hp;
                *reinterpret_cast<uint32_t*>(Cl + (size_t)r2 * N + col) = lp;
            } else {
                float2 bv = *reinterpret_cast<const float2*>(bvec + col);
                float2 o1 = {d[0] + bv.x, d[1] + bv.y};
                float2 o2 = {d[2] + bv.x, d[3] + bv.y};
                *reinterpret_cast<float2*>(Cf + (size_t)r1 * N + col) = o1;
                *reinterpret_cast<float2*>(Cf + (size_t)r2 * N + col) = o2;
            }
        }
    }
}

// ---------------- attention via mma.sync ----------------
// CTA = 128 queries x 1 head, 256 threads (8 warps, 2x4).
// smem: Q (32KB) | KV stage0 (64KB) | KV stage1 (64KB) | Ph (32KB) | Pl (32KB)
constexpr uint32_t AQ  = 0;
constexpr uint32_t AKV0 = 32768;
constexpr uint32_t AKV1 = 98304;
constexpr uint32_t AP  = 163840;
constexpr uint32_t APL = 196608;
constexpr int ATTN_SMEM = 229376;

__global__ void __launch_bounds__(256)
attn_tc(const __nv_bfloat16* __restrict__ Qh, const __nv_bfloat16* __restrict__ Ql,
        const __nv_bfloat16* __restrict__ Kh, const __nv_bfloat16* __restrict__ Kl,
        const __nv_bfloat16* __restrict__ Vh, const __nv_bfloat16* __restrict__ Vl,
        const float* __restrict__ bias,
        __nv_bfloat16* __restrict__ Ch, __nv_bfloat16* __restrict__ Cl)
{
    extern __shared__ char sm[];
    const uint32_t sb = s2u(sm);
    const int tid  = threadIdx.x;
    const int wid  = tid >> 5;
    const int lane = tid & 31;
    const int m0w  = (wid >> 2) * 64;
    const int n0w  = (wid & 3) * 32;
    const int q0   = blockIdx.x * 128;
    const int hoff = blockIdx.y * HD;
    const int sub = lane >> 3, lr = lane & 7;
    const float SC = 0.03125f;

    // prologue: Q tiles + KV tile 0, one cp.async group
    cp_tile(sb + AQ,          Qh + (size_t)q0 * E + hoff, E, tid);
    cp_tile(sb + AQ + 16384,  Ql + (size_t)q0 * E + hoff, E, tid);
    cp_tile(sb + AKV0,         Kh + hoff, E, tid);
    cp_tile(sb + AKV0 + 16384, Kl + hoff, E, tid);
    cp_tile(sb + AKV0 + 32768, Vh + hoff, E, tid);
    cp_tile(sb + AKV0 + 49152, Vl + hoff, E, tid);
    CP_COMMIT();

    float acc_o[4][2][4];
#pragma unroll
    for (int i = 0; i < 4; i++)
#pragma unroll
        for (int j = 0; j < 2; j++)
#pragma unroll
            for (int k = 0; k < 4; k++) acc_o[i][j][k] = 0.f;
    float lsum[4][2];
#pragma unroll
    for (int i = 0; i < 4; i++) { lsum[i][0] = 0.f; lsum[i][1] = 0.f; }

    for (int kt = 0; kt < L / 128; kt++) {
        const int kb = kt * 128;
        if (kt + 1 < L / 128) {
            uint32_t base = sb + (((kt + 1) & 1) ? AKV1 : AKV0);
            const __nv_bfloat16* kh = Kh + (size_t)(kb + 128) * E + hoff;
            const __nv_bfloat16* kl = Kl + (size_t)(kb + 128) * E + hoff;
            const __nv_bfloat16* vh = Vh + (size_t)(kb + 128) * E + hoff;
            const __nv_bfloat16* vl = Vl + (size_t)(kb + 128) * E + hoff;
            cp_tile(base,         kh, E, tid);
            cp_tile(base + 16384, kl, E, tid);
            cp_tile(base + 32768, vh, E, tid);
            cp_tile(base + 49152, vl, E, tid);
            CP_COMMIT();
            CP_WAIT1();
        } else {
            CP_WAIT0();
        }
        __syncthreads();

        const uint32_t bkv = sb + ((kt & 1) ? AKV1 : AKV0);

        // ---- S = Q @ K^T ----
        float acc_s[4][4][4];
#pragma unroll
        for (int i = 0; i < 4; i++)
#pragma unroll
            for (int j = 0; j < 4; j++)
#pragma unroll
                for (int k = 0; k < 4; k++) acc_s[i][j][k] = 0.f;

#pragma unroll
        for (int ks = 0; ks < 4; ks++) {
            const int ch = ks * 2 + (sub >> 1);
            uint32_t ah[4][4], al[4][4], bh[4][2], bl[4][2];
#pragma unroll
            for (int mi = 0; mi < 4; mi++) {
                int r = m0w + mi * 16 + (sub & 1) * 8 + lr;
                uint32_t off = sw128((uint32_t)(r * 128 + ch * 16));
                LDSM4(ah[mi][0], ah[mi][1], ah[mi][2], ah[mi][3], sb + AQ + off);
                LDSM4(al[mi][0], al[mi][1], al[mi][2], al[mi][3], sb + AQ + 16384 + off);
            }
#pragma unroll
            for (int ng = 0; ng < 2; ng++) {
                int r = n0w + ng * 16 + (sub & 1) * 8 + lr;
                uint32_t off = sw128((uint32_t)(r * 128 + ch * 16));
                uint32_t t0, t1, t2, t3;
                LDSM4(t0, t1, t2, t3, bkv + off);
                bh[2*ng][0] = t0; bh[2*ng][1] = t2;
                bh[2*ng+1][0] = t1; bh[2*ng+1][1] = t3;
                LDSM4(t0, t1, t2, t3, bkv + 16384 + off);
                bl[2*ng][0] = t0; bl[2*ng][1] = t2;
                bl[2*ng+1][0] = t1; bl[2*ng+1][1] = t3;
            }
#pragma unroll
            for (int mi = 0; mi < 4; mi++)
#pragma unroll
                for (int ni = 0; ni < 4; ni++) {
                    MMA16816(acc_s[mi][ni], ah[mi], bh[ni]);
                    MMA16816(acc_s[mi][ni], ah[mi], bl[ni]);
                    MMA16816(acc_s[mi][ni], al[mi], bh[ni]);
                }
        }

        // ---- bias + exp + P store (split bf16, XOR-swizzled smem) ----
#pragma unroll
        for (int mi = 0; mi < 4; mi++) {
            const int lr1 = m0w + mi * 16 + (lane >> 2);
            const int lr2 = lr1 + 8;
            const float* bp1 = bias + (size_t)(q0 + lr1) * L + kb;
            const float* bp2 = bias + (size_t)(q0 + lr2) * L + kb;
#pragma unroll
            for (int ni = 0; ni < 4; ni++) {
                const int lc = n0w + ni * 8 + (lane & 3) * 2;
                float2 b1 = *reinterpret_cast<const float2*>(bp1 + lc);
                float2 b2 = *reinterpret_cast<const float2*>(bp2 + lc);
                float* d = acc_s[mi][ni];
                float p0 = __expf((d[0] + b1.x) * SC);
                float p1 = __expf((d[1] + b1.y) * SC);
                float p2 = __expf((d[2] + b2.x) * SC);
                float p3 = __expf((d[3] + b2.y) * SC);
                lsum[mi][0] += p0 + p1;
                lsum[mi][1] += p2 + p3;
                uint32_t hp, lp;
                const int chn = lc >> 3, cb = (lc & 7) * 2;
                split2(p0, p1, hp, lp);
                uint32_t a1 = lr1 * 256 + (((uint32_t)(chn ^ (lr1 & 7))) << 4) + cb;
                *reinterpret_cast<uint32_t*>(sm + AP  + a1) = hp;
                *reinterpret_cast<uint32_t*>(sm + APL + a1) = lp;
                split2(p2, p3, hp, lp);
                uint32_t a2 = lr2 * 256 + (((uint32_t)(chn ^ (lr2 & 7))) << 4) + cb;
                *reinterpret_cast<uint32_t*>(sm + AP  + a2) = hp;
                *reinterpret_cast<uint32_t*>(sm + APL + a2) = lp;
            }
        }
        __syncthreads();

        // ---- O += P @ V ----
#pragma unroll
        for (int ks = 0; ks < 8; ks++) {
            const int ch = ks * 2 + (sub >> 1);
            uint32_t ah[4][4], al[4][4], bh[2][2], bl[2][2];
#pragma unroll
            for (int mi = 0; mi < 4; mi++) {
                int r = m0w + mi * 16 + (sub & 1) * 8 + lr;
                uint32_t off = (uint32_t)(r * 256) + (((uint32_t)(ch ^ (r & 7))) << 4);
                LDSM4(ah[mi][0], ah[mi][1], ah[mi][2], ah[mi][3], sb + AP + off);
                LDSM4(al[mi][0], al[mi][1], al[mi][2], al[mi][3], sb + APL + off);
            }
            {
                int rv = ks * 16 + (sub >> 1) * 8 + lr;
                int cv = (wid & 3) * 2 + (sub & 1);
                uint32_t off = sw128((uint32_t)(rv * 128 + cv * 16));
                uint32_t t0, t1, t2, t3;
                LDSM4T(t0, t1, t2, t3, bkv + 32768 + off);
                bh[0][0] = t0; bh[0][1] = t2; bh[1][0] = t1; bh[1][1] = t3;
                LDSM4T(t0, t1, t2, t3, bkv + 49152 + off);
                bl[0][0] = t0; bl[0][1] = t2; bl[1][0] = t1; bl[1][1] = t3;
            }
#pragma unroll
            for (int mi = 0; mi < 4; mi++)
#pragma unroll
                for (int nf = 0; nf < 2; nf++) {
                    MMA16816(acc_o[mi][nf], ah[mi], bh[nf]);
                    MMA16816(acc_o[mi][nf], ah[mi], bl[nf]);
                    MMA16816(acc_o[mi][nf], al[mi], bh[nf]);
                }
        }
        __syncthreads();
    }

    // ---- row-sum reduction (reuse P smem as float scratch) ----
    float* smf = reinterpret_cast<float*>(sm + AP);       // [128][4]
    float* inv = smf + 512;                                // [128]
#pragma unroll
    for (int mi = 0; mi < 4; mi++)
#pragma unroll
        for (int h = 0; h < 2; h++) {
            float v = lsum[mi][h];
            v += __shfl_xor_sync(0xffffffffu, v, 1);
            v += __shfl_xor_sync(0xffffffffu, v, 2);
            if ((lane & 3) == 0) {
                int row = m0w + mi * 16 + h * 8 + (lane >> 2);
                smf[row * 4 + (wid & 3)] = v;
            }
        }
    __syncthreads();
    if (tid < 128) {
        float s = smf[tid * 4] + smf[tid * 4 + 1] + smf[tid * 4 + 2] + smf[tid * 4 + 3];
        inv[tid] = 1.0f / s;
    }
    __syncthreads();

    // ---- normalize + write split-bf16 context ----
#pragma unroll
    for (int mi = 0; mi < 4; mi++) {
        const int lr1 = m0w + mi * 16 + (lane >> 2);
        const int lr2 = lr1 + 8;
        const float i1 = inv[lr1], i2 = inv[lr2];
#pragma unroll
        for (int nf = 0; nf < 2; nf++) {
            const int c = (wid & 3) * 16 + nf * 8 + (lane & 3) * 2;
            float* d = acc_o[mi][nf];
            uint32_t hp, lp;
            split2(d[0] * i1, d[1] * i1, hp, lp);
            size_t idx = (size_t)(q0 + lr1) * E + hoff + c;
            *reinterpret_cast<uint32_t*>(Ch + idx) = hp;
            *reinterpret_cast<uint32_t*>(Cl + idx) = lp;
            split2(d[2] * i2, d[3] * i2, hp, lp);
            idx = (size_t)(q0 + lr2) * E + hoff + c;
            *reinterpret_cast<uint32_t*>(Ch + idx) = hp;
            *reinterpret_cast<uint32_t*>(Cl + idx) = lp;
        }
    }
}

// ---------------- host side ----------------
extern "C" void kernel_launch(void* const* d_in, const int* in_sizes, int n_in,
                              void* d_out, int out_size)
{
    const float* values = (const float*)d_in[0];
    const float* keys   = (const float*)d_in[1];
    const float* query  = (const float*)d_in[2];
    const float* dist   = (const float*)d_in[3];
    const float* Wv     = (const float*)d_in[4];
    const float* Wk     = (const float*)d_in[5];
    const float* Wq     = (const float*)d_in[6];
    const float* Wo     = (const float*)d_in[7];
    const float* bo     = (const float*)d_in[8];
    float* out = (float*)d_out;

    __nv_bfloat16 *xqh, *xql, *xkh, *xkl, *xvh, *xvl;
    __nv_bfloat16 *wqh, *wql, *wkh, *wkl, *wvh, *wvl, *woh, *wol;
    __nv_bfloat16 *pqh, *pql, *pkh, *pkl, *pvh, *pvl, *cxh, *cxl;
    float* biasb;
    cudaGetSymbolAddress((void**)&xqh, g_xqh); cudaGetSymbolAddress((void**)&xql, g_xql);
    cudaGetSymbolAddress((void**)&xkh, g_xkh); cudaGetSymbolAddress((void**)&xkl, g_xkl);
    cudaGetSymbolAddress((void**)&xvh, g_xvh); cudaGetSymbolAddress((void**)&xvl, g_xvl);
    cudaGetSymbolAddress((void**)&wqh, g_wqh); cudaGetSymbolAddress((void**)&wql, g_wql);
    cudaGetSymbolAddress((void**)&wkh, g_wkh); cudaGetSymbolAddress((void**)&wkl, g_wkl);
    cudaGetSymbolAddress((void**)&wvh, g_wvh); cudaGetSymbolAddress((void**)&wvl, g_wvl);
    cudaGetSymbolAddress((void**)&woh, g_woh); cudaGetSymbolAddress((void**)&wol, g_wol);
    cudaGetSymbolAddress((void**)&pqh, g_pqh); cudaGetSymbolAddress((void**)&pql, g_pql);
    cudaGetSymbolAddress((void**)&pkh, g_pkh); cudaGetSymbolAddress((void**)&pkl, g_pkl);
    cudaGetSymbolAddress((void**)&pvh, g_pvh); cudaGetSymbolAddress((void**)&pvl, g_pvl);
    cudaGetSymbolAddress((void**)&cxh, g_cxh); cudaGetSymbolAddress((void**)&cxl, g_cxl);
    cudaGetSymbolAddress((void**)&biasb, g_bias);

    cudaFuncSetAttribute(gemm_tc<0>, cudaFuncAttributeMaxDynamicSharedMemorySize, GEMM_SMEM);
    cudaFuncSetAttribute(gemm_tc<1>, cudaFuncAttributeMaxDynamicSharedMemorySize, GEMM_SMEM);
    cudaFuncSetAttribute(attn_tc,    cudaFuncAttributeMaxDynamicSharedMemorySize, ATTN_SMEM);

    const int nLE = L * E, nEE = E * E, nLL = L * L;
    convert_split<<<nLE / 4 / 256, 256>>>(query,  xqh, xql, nLE);
    convert_split<<<nLE / 4 / 256, 256>>>(keys,   xkh, xkl, nLE);
    convert_split<<<nLE / 4 / 256, 256>>>(values, xvh, xvl, nLE);
    convert_split<<<nEE / 4 / 256, 256>>>(Wq, wqh, wql, nEE);
    convert_split<<<nEE / 4 / 256, 256>>>(Wk, wkh, wkl, nEE);
    convert_split<<<nEE / 4 / 256, 256>>>(Wv, wvh, wvl, nEE);
    convert_split<<<nEE / 4 / 256, 256>>>(Wo, woh, wol, nEE);
    bias_prep<<<nLL / 4 / 256, 256>>>(dist, biasb, nLL);

    dim3 gp(E / 128, L / 128);   // (8, 16)
    gemm_tc<0><<<gp, 256, GEMM_SMEM>>>(xqh, xql, wqh, wql, pqh, pql, nullptr, nullptr, L, E, E);
    gemm_tc<0><<<gp, 256, GEMM_SMEM>>>(xkh, xkl, wkh, wkl, pkh, pkl, nullptr, nullptr, L, E, E);
    gemm_tc<0><<<gp, 256, GEMM_SMEM>>>(xvh, xvl, wvh, wvl, pvh, pvl, nullptr, nullptr, L, E, E);

    attn_tc<<<dim3(L / 128, NH), 256, ATTN_SMEM>>>(pqh, pql, pkh, pkl, pvh, pvl,
                                                   biasb, cxh, cxl);

    gemm_tc<1><<<gp, 256, GEMM_SMEM>>>(cxh, cxl, woh, wol, nullptr, nullptr, out, bo, L, E, E);
}

// round 5
// speedup vs baseline: 3.8926x; 1.3000x over previous
#include <cuda_runtime.h>
#include <cuda_bf16.h>
#include <cstdint>

// ---------------- problem constants ----------------
constexpr int L  = 2048;
constexpr int E  = 1024;
constexpr int NH = 16;
constexpr int HD = 64;
constexpr float KSCALE = 0.04508422002778011f;   // log2(e)/32

// ---------------- device scratch ----------------
__device__ __nv_bfloat16 g_xqh[L * E], g_xql[L * E];
__device__ __nv_bfloat16 g_xkh[L * E], g_xkl[L * E];
__device__ __nv_bfloat16 g_xvh[L * E], g_xvl[L * E];
__device__ __nv_bfloat16 g_wqh[E * E], g_wql[E * E];
__device__ __nv_bfloat16 g_wkh[E * E], g_wkl[E * E];
__device__ __nv_bfloat16 g_wvh[E * E], g_wvl[E * E];
__device__ __nv_bfloat16 g_woh[E * E], g_wol[E * E];
__device__ __nv_bfloat16 g_pq[L * E];                  // projected Q (scaled, 1-term)
__device__ __nv_bfloat16 g_pk[L * E];                  // projected K (1-term)
__device__ __nv_bfloat16 g_pvh[L * E], g_pvl[L * E];   // projected V split
__device__ __nv_bfloat16 g_cxh[L * E], g_cxl[L * E];   // context split
__device__ __nv_bfloat16 g_biasbf[(size_t)L * L];      // bias * log2e/32, bf16

// ---------------- helpers ----------------
__device__ __forceinline__ uint32_t s2u(const void* p) {
    uint32_t a;
    asm("{ .reg .u64 t; cvta.to.shared.u64 t, %1; cvt.u32.u64 %0, t; }"
        : "=r"(a) : "l"(p));
    return a;
}
__device__ __forceinline__ uint32_t sw128(uint32_t off) {
    return off ^ ((off >> 3) & 0x70);
}
__device__ __forceinline__ float ex2f(float x) {
    float r; asm("ex2.approx.f32 %0, %1;" : "=f"(r) : "f"(x)); return r;
}
// pack two floats as bf16x2 (round-to-nearest), lo in low half
__device__ __forceinline__ uint32_t pack_rn(float lo, float hi) {
    uint32_t r;
    asm("cvt.rn.bf16x2.f32 %0, %1, %2;" : "=r"(r) : "f"(hi), "f"(lo));
    return r;
}
// truncation split of a pair: hp = hi16 halves, lp = rn-bf16 of residuals
__device__ __forceinline__ void split_trunc2(float f0, float f1,
                                             uint32_t& hp, uint32_t& lp) {
    uint32_t b0 = __float_as_uint(f0), b1 = __float_as_uint(f1);
    asm("prmt.b32 %0, %1, %2, 0x7632;" : "=r"(hp) : "r"(b0), "r"(b1));
    float l0 = f0 - __uint_as_float(b0 & 0xffff0000u);
    float l1 = f1 - __uint_as_float(b1 & 0xffff0000u);
    lp = pack_rn(l0, l1);
}

#define CP_ASYNC16(dst, src) \
    asm volatile("cp.async.cg.shared.global [%0], [%1], 16;" :: "r"(dst), "l"(src))
#define CP_COMMIT() asm volatile("cp.async.commit_group;" ::: "memory")
#define CP_WAIT1()  asm volatile("cp.async.wait_group 1;" ::: "memory")
#define CP_WAIT0()  asm volatile("cp.async.wait_group 0;" ::: "memory")

#define LDSM4(r0, r1, r2, r3, a) \
    asm volatile("ldmatrix.sync.aligned.m8n8.x4.shared.b16 {%0,%1,%2,%3}, [%4];" \
        : "=r"(r0), "=r"(r1), "=r"(r2), "=r"(r3) : "r"(a))
#define LDSM4T(r0, r1, r2, r3, a) \
    asm volatile("ldmatrix.sync.aligned.m8n8.x4.trans.shared.b16 {%0,%1,%2,%3}, [%4];" \
        : "=r"(r0), "=r"(r1), "=r"(r2), "=r"(r3) : "r"(a))

#define MMA16816(d, a, b) \
    asm volatile("mma.sync.aligned.m16n8k16.row.col.f32.bf16.bf16.f32 " \
        "{%0,%1,%2,%3}, {%4,%5,%6,%7}, {%8,%9}, {%0,%1,%2,%3};" \
        : "+f"((d)[0]), "+f"((d)[1]), "+f"((d)[2]), "+f"((d)[3]) \
        : "r"((a)[0]), "r"((a)[1]), "r"((a)[2]), "r"((a)[3]), \
          "r"((b)[0]), "r"((b)[1]))

// cp.async one [128 x 64] bf16 tile into SW128-swizzled smem (256 threads)
__device__ __forceinline__ void cp_tile(uint32_t dst, const __nv_bfloat16* src,
                                        int ld, int tid) {
#pragma unroll
    for (int i = 0; i < 4; i++) {
        int u   = i * 256 + tid;
        int row = u >> 3;
        int ch  = u & 7;
        uint32_t d = dst + sw128((uint32_t)(row * 128 + ch * 16));
        CP_ASYNC16(d, src + (size_t)row * ld + ch * 8);
    }
}

// ---------------- fused conversion (single launch, all splits) ----------------
__device__ __forceinline__ void conv2_at(const float* s, __nv_bfloat16* dh,
                                         __nv_bfloat16* dl, int i) {
    float4 v = *reinterpret_cast<const float4*>(s + i);
    uint32_t h0, l0, h1, l1;
    split_trunc2(v.x, v.y, h0, l0);
    split_trunc2(v.z, v.w, h1, l1);
    uint2 oh = {h0, h1}, ol = {l0, l1};
    *reinterpret_cast<uint2*>(dh + i) = oh;
    *reinterpret_cast<uint2*>(dl + i) = ol;
}

constexpr int LE = L * E, EE = E * E;

__global__ void conv_all(const float* q, const float* k, const float* v,
                         const float* Wq, const float* Wk,
                         const float* Wv, const float* Wo,
                         __nv_bfloat16* xqh, __nv_bfloat16* xql,
                         __nv_bfloat16* xkh, __nv_bfloat16* xkl,
                         __nv_bfloat16* xvh, __nv_bfloat16* xvl,
                         __nv_bfloat16* wqh, __nv_bfloat16* wql,
                         __nv_bfloat16* wkh, __nv_bfloat16* wkl,
                         __nv_bfloat16* wvh, __nv_bfloat16* wvl,
                         __nv_bfloat16* woh, __nv_bfloat16* wol)
{
    int i = (blockIdx.x * blockDim.x + threadIdx.x) * 4;
    if (i < LE) { conv2_at(q, xqh, xql, i); return; }
    i -= LE;
    if (i < LE) { conv2_at(k, xkh, xkl, i); return; }
    i -= LE;
    if (i < LE) { conv2_at(v, xvh, xvl, i); return; }
    i -= LE;
    if (i < EE) { conv2_at(Wq, wqh, wql, i); return; }
    i -= EE;
    if (i < EE) { conv2_at(Wk, wkh, wkl, i); return; }
    i -= EE;
    if (i < EE) { conv2_at(Wv, wvh, wvl, i); return; }
    i -= EE;
    conv2_at(Wo, woh, wol, i);
}

// ---------------- bias table: bf16( log2e/32 * 1/(d+1) ) ----------------
__global__ void bias_prep(const float* __restrict__ d, __nv_bfloat16* __restrict__ b)
{
    int i = (blockIdx.x * blockDim.x + threadIdx.x) * 4;
    float4 v = *reinterpret_cast<const float4*>(d + i);
    float o0 = (v.x == 0.f) ? 0.f : KSCALE / (v.x + 1.f);
    float o1 = (v.y == 0.f) ? 0.f : KSCALE / (v.y + 1.f);
    float o2 = (v.z == 0.f) ? 0.f : KSCALE / (v.z + 1.f);
    float o3 = (v.w == 0.f) ? 0.f : KSCALE / (v.w + 1.f);
    uint2 o = { pack_rn(o0, o1), pack_rn(o2, o3) };
    *reinterpret_cast<uint2*>(b + i) = o;
}

// ---------------- GEMM: C = A @ B^T via mma.sync (3-term split) ----------------
// OMODE: 0 = bf16 out scaled by oscale; 1 = split-bf16 out; 2 = fp32 + bias
constexpr int GEMM_SMEM = 131072;

template <int OMODE>
__global__ void __launch_bounds__(256)
gemm_tc(const __nv_bfloat16* __restrict__ Ah, const __nv_bfloat16* __restrict__ Al,
        const __nv_bfloat16* __restrict__ Bh, const __nv_bfloat16* __restrict__ Bl,
        __nv_bfloat16* __restrict__ Ch, __nv_bfloat16* __restrict__ Cl,
        float* __restrict__ Cf, const float* __restrict__ bvec,
        float oscale, int M, int N, int K)
{
    extern __shared__ char sm[];
    const uint32_t sb = s2u(sm);
    const int tid  = threadIdx.x;
    const int wid  = tid >> 5;
    const int lane = tid & 31;
    const int m0w  = (wid >> 2) * 64;
    const int n0w  = (wid & 3) * 32;
    const int m0 = blockIdx.y * 128;
    const int n0 = blockIdx.x * 128;
    const int sub = lane >> 3, lr = lane & 7;

    float acc[4][4][4];
#pragma unroll
    for (int i = 0; i < 4; i++)
#pragma unroll
        for (int j = 0; j < 4; j++)
#pragma unroll
            for (int k = 0; k < 4; k++) acc[i][j][k] = 0.f;

    const int NC = K / 64;

    {   // prologue chunk 0
        cp_tile(sb,         Ah + (size_t)m0 * K, K, tid);
        cp_tile(sb + 16384, Al + (size_t)m0 * K, K, tid);
        cp_tile(sb + 32768, Bh + (size_t)n0 * K, K, tid);
        cp_tile(sb + 49152, Bl + (size_t)n0 * K, K, tid);
        CP_COMMIT();
    }

    for (int kc = 0; kc < NC; kc++) {
        if (kc + 1 < NC) {
            uint32_t base = sb + ((kc + 1) & 1) * 65536;
            const int k0 = (kc + 1) * 64;
            cp_tile(base,         Ah + (size_t)m0 * K + k0, K, tid);
            cp_tile(base + 16384, Al + (size_t)m0 * K + k0, K, tid);
            cp_tile(base + 32768, Bh + (size_t)n0 * K + k0, K, tid);
            cp_tile(base + 49152, Bl + (size_t)n0 * K + k0, K, tid);
            CP_COMMIT();
            CP_WAIT1();
        } else {
            CP_WAIT0();
        }
        __syncthreads();

        const uint32_t base = sb + (kc & 1) * 65536;
#pragma unroll
        for (int ks = 0; ks < 4; ks++) {
            const int ch = ks * 2 + (sub >> 1);
            uint32_t ah[4][4], al[4][4], bh[4][2], bl[4][2];
#pragma unroll
            for (int mi = 0; mi < 4; mi++) {
                int r = m0w + mi * 16 + (sub & 1) * 8 + lr;
                uint32_t off = sw128((uint32_t)(r * 128 + ch * 16));
                LDSM4(ah[mi][0], ah[mi][1], ah[mi][2], ah[mi][3], base + off);
                LDSM4(al[mi][0], al[mi][1], al[mi][2], al[mi][3], base + 16384 + off);
            }
#pragma unroll
            for (int ng = 0; ng < 2; ng++) {
                int r = n0w + ng * 16 + (sub & 1) * 8 + lr;
                uint32_t off = sw128((uint32_t)(r * 128 + ch * 16));
                uint32_t t0, t1, t2, t3;
                LDSM4(t0, t1, t2, t3, base + 32768 + off);
                bh[2*ng][0] = t0; bh[2*ng][1] = t2;
                bh[2*ng+1][0] = t1; bh[2*ng+1][1] = t3;
                LDSM4(t0, t1, t2, t3, base + 49152 + off);
                bl[2*ng][0] = t0; bl[2*ng][1] = t2;
                bl[2*ng+1][0] = t1; bl[2*ng+1][1] = t3;
            }
#pragma unroll
            for (int mi = 0; mi < 4; mi++)
#pragma unroll
                for (int ni = 0; ni < 4; ni++) {
                    MMA16816(acc[mi][ni], ah[mi], bh[ni]);
                    MMA16816(acc[mi][ni], ah[mi], bl[ni]);
                    MMA16816(acc[mi][ni], al[mi], bh[ni]);
                }
        }
        __syncthreads();
    }

    // epilogue
#pragma unroll
    for (int mi = 0; mi < 4; mi++) {
        int r1 = m0 + m0w + mi * 16 + (lane >> 2);
        int r2 = r1 + 8;
#pragma unroll
        for (int ni = 0; ni < 4; ni++) {
            int col = n0 + n0w + ni * 8 + (lane & 3) * 2;
            float* d = acc[mi][ni];
            if (OMODE == 0) {
                *reinterpret_cast<uint32_t*>(Ch + (size_t)r1 * N + col) =
                    pack_rn(d[0] * oscale, d[1] * oscale);
                *reinterpret_cast<uint32_t*>(Ch + (size_t)r2 * N + col) =
                    pack_rn(d[2] * oscale, d[3] * oscale);
            } else if (OMODE == 1) {
                uint32_t hp, lp;
                split_trunc2(d[0], d[1], hp, lp);
                *reinterpret_cast<uint32_t*>(Ch + (size_t)r1 * N + col) = hp;
                *reinterpret_cast<uint32_t*>(Cl + (size_t)r1 * N + col) = lp;
                split_trunc2(d[2], d[3], hp, lp);
                *reinterpret_cast<uint32_t*>(Ch + (size_t)r2 * N + col) = hp;
                *reinterpret_cast<uint32_t*>(Cl + (size_t)r2 * N + col) = lp;
            } else {
                float2 bv = *reinterpret_cast<const float2*>(bvec + col);
                float2 o1 = {d[0] + bv.x, d[1] + bv.y};
                float2 o2 = {d[2] + bv.x, d[3] + bv.y};
                *reinterpret_cast<float2*>(Cf + (size_t)r1 * N + col) = o1;
                *reinterpret_cast<float2*>(Cf + (size_t)r2 * N + col) = o2;
            }
        }
    }
}

// ---------------- attention ----------------
// CTA = 128 queries x 1 head, 256 threads (8 warps, 2x4).
// Q pre-scaled by log2e/32 (1-term); K 1-term; p = ex2(S + biasbf); PV 3-term.
// smem: Q(16K) | stage0 {K,Vh,Vl}(48K) | stage1(48K) | Ph(32K) | Pl(32K)
constexpr uint32_t AQ   = 0;
constexpr uint32_t AKV0 = 16384;
constexpr uint32_t AKV1 = 65536;
constexpr uint32_t AP   = 114688;
constexpr uint32_t APL  = 147456;
constexpr int ATTN_SMEM = 180224;

__global__ void __launch_bounds__(256, 1)
attn_tc(const __nv_bfloat16* __restrict__ Q,
        const __nv_bfloat16* __restrict__ Kp,
        const __nv_bfloat16* __restrict__ Vh, const __nv_bfloat16* __restrict__ Vl,
        const __nv_bfloat16* __restrict__ biasbf,
        __nv_bfloat16* __restrict__ Ch, __nv_bfloat16* __restrict__ Cl)
{
    extern __shared__ char sm[];
    const uint32_t sb = s2u(sm);
    const int tid  = threadIdx.x;
    const int wid  = tid >> 5;
    const int lane = tid & 31;
    const int m0w  = (wid >> 2) * 64;
    const int n0w  = (wid & 3) * 32;
    const int q0   = blockIdx.x * 128;
    const int hoff = blockIdx.y * HD;
    const int sub = lane >> 3, lr = lane & 7;

    // prologue: Q + KV0 in one group
    cp_tile(sb + AQ, Q + (size_t)q0 * E + hoff, E, tid);
    cp_tile(sb + AKV0,         Kp + hoff, E, tid);
    cp_tile(sb + AKV0 + 16384, Vh + hoff, E, tid);
    cp_tile(sb + AKV0 + 32768, Vl + hoff, E, tid);
    CP_COMMIT();

    float acc_o[4][2][4];
#pragma unroll
    for (int i = 0; i < 4; i++)
#pragma unroll
        for (int j = 0; j < 2; j++)
#pragma unroll
            for (int k = 0; k < 4; k++) acc_o[i][j][k] = 0.f;
    float lsum[4][2];
#pragma unroll
    for (int i = 0; i < 4; i++) { lsum[i][0] = 0.f; lsum[i][1] = 0.f; }

    for (int kt = 0; kt < L / 128; kt++) {
        const int kb = kt * 128;
        if (kt + 1 < L / 128) {
            uint32_t base = sb + (((kt + 1) & 1) ? AKV1 : AKV0);
            const size_t ro = (size_t)(kb + 128) * E + hoff;
            cp_tile(base,         Kp + ro, E, tid);
            cp_tile(base + 16384, Vh + ro, E, tid);
            cp_tile(base + 32768, Vl + ro, E, tid);
            CP_COMMIT();
            CP_WAIT1();
        } else {
            CP_WAIT0();
        }
        __syncthreads();

        const uint32_t bkv = sb + ((kt & 1) ? AKV1 : AKV0);

        // ---- S = Q @ K^T (1-term bf16) ----
        float acc_s[4][4][4];
#pragma unroll
        for (int i = 0; i < 4; i++)
#pragma unroll
            for (int j = 0; j < 4; j++)
#pragma unroll
                for (int k = 0; k < 4; k++) acc_s[i][j][k] = 0.f;

#pragma unroll
        for (int ks = 0; ks < 4; ks++) {
            const int ch = ks * 2 + (sub >> 1);
            uint32_t qa[4][4], bh[4][2];
#pragma unroll
            for (int mi = 0; mi < 4; mi++) {
                int r = m0w + mi * 16 + (sub & 1) * 8 + lr;
                uint32_t off = sw128((uint32_t)(r * 128 + ch * 16));
                LDSM4(qa[mi][0], qa[mi][1], qa[mi][2], qa[mi][3], sb + AQ + off);
            }
#pragma unroll
            for (int ng = 0; ng < 2; ng++) {
                int r = n0w + ng * 16 + (sub & 1) * 8 + lr;
                uint32_t off = sw128((uint32_t)(r * 128 + ch * 16));
                uint32_t t0, t1, t2, t3;
                LDSM4(t0, t1, t2, t3, bkv + off);
                bh[2*ng][0] = t0; bh[2*ng][1] = t2;
                bh[2*ng+1][0] = t1; bh[2*ng+1][1] = t3;
            }
#pragma unroll
            for (int mi = 0; mi < 4; mi++)
#pragma unroll
                for (int ni = 0; ni < 4; ni++)
                    MMA16816(acc_s[mi][ni], qa[mi], bh[ni]);
        }

        // ---- p = ex2(S + bias); store split P ----
#pragma unroll
        for (int mi = 0; mi < 4; mi++) {
            const int lr1 = m0w + mi * 16 + (lane >> 2);
            const int lr2 = lr1 + 8;
            const uint32_t* bp1 = reinterpret_cast<const uint32_t*>(
                biasbf + (size_t)(q0 + lr1) * L + kb);
            const uint32_t* bp2 = reinterpret_cast<const uint32_t*>(
                biasbf + (size_t)(q0 + lr2) * L + kb);
#pragma unroll
            for (int ni = 0; ni < 4; ni++) {
                const int lc = n0w + ni * 8 + (lane & 3) * 2;
                uint32_t pk1 = bp1[lc >> 1];
                uint32_t pk2 = bp2[lc >> 1];
                float* d = acc_s[mi][ni];
                float p0 = ex2f(d[0] + __uint_as_float(pk1 << 16));
                float p1 = ex2f(d[1] + __uint_as_float(pk1 & 0xffff0000u));
                float p2 = ex2f(d[2] + __uint_as_float(pk2 << 16));
                float p3 = ex2f(d[3] + __uint_as_float(pk2 & 0xffff0000u));
                lsum[mi][0] += p0 + p1;
                lsum[mi][1] += p2 + p3;
                uint32_t hp, lp;
                const int chn = lc >> 3, cb = (lc & 7) * 2;
                split_trunc2(p0, p1, hp, lp);
                uint32_t a1 = lr1 * 256 + (((uint32_t)(chn ^ (lr1 & 7))) << 4) + cb;
                *reinterpret_cast<uint32_t*>(sm + AP  + a1) = hp;
                *reinterpret_cast<uint32_t*>(sm + APL + a1) = lp;
                split_trunc2(p2, p3, hp, lp);
                uint32_t a2 = lr2 * 256 + (((uint32_t)(chn ^ (lr2 & 7))) << 4) + cb;
                *reinterpret_cast<uint32_t*>(sm + AP  + a2) = hp;
                *reinterpret_cast<uint32_t*>(sm + APL + a2) = lp;
            }
        }
        __syncthreads();

        // ---- O += P @ V (3-term) ----
#pragma unroll
        for (int ks = 0; ks < 8; ks++) {
            const int ch = ks * 2 + (sub >> 1);
            uint32_t ah[4][4], al[4][4], bh[2][2], bl[2][2];
#pragma unroll
            for (int mi = 0; mi < 4; mi++) {
                int r = m0w + mi * 16 + (sub & 1) * 8 + lr;
                uint32_t off = (uint32_t)(r * 256) + (((uint32_t)(ch ^ (r & 7))) << 4);
                LDSM4(ah[mi][0], ah[mi][1], ah[mi][2], ah[mi][3], sb + AP + off);
                LDSM4(al[mi][0], al[mi][1], al[mi][2], al[mi][3], sb + APL + off);
            }
            {
                int rv = ks * 16 + (sub >> 1) * 8 + lr;
                int cv = (wid & 3) * 2 + (sub & 1);
                uint32_t off = sw128((uint32_t)(rv * 128 + cv * 16));
                uint32_t t0, t1, t2, t3;
                LDSM4T(t0, t1, t2, t3, bkv + 16384 + off);
                bh[0][0] = t0; bh[0][1] = t2; bh[1][0] = t1; bh[1][1] = t3;
                LDSM4T(t0, t1, t2, t3, bkv + 32768 + off);
                bl[0][0] = t0; bl[0][1] = t2; bl[1][0] = t1; bl[1][1] = t3;
            }
#pragma unroll
            for (int mi = 0; mi < 4; mi++)
#pragma unroll
                for (int nf = 0; nf < 2; nf++) {
                    MMA16816(acc_o[mi][nf], ah[mi], bh[nf]);
                    MMA16816(acc_o[mi][nf], ah[mi], bl[nf]);
                    MMA16816(acc_o[mi][nf], al[mi], bh[nf]);
                }
        }
        __syncthreads();
    }

    // ---- row-sum reduction (reuse P smem) ----
    float* smf = reinterpret_cast<float*>(sm + AP);
    float* inv = smf + 512;
#pragma unroll
    for (int mi = 0; mi < 4; mi++)
#pragma unroll
        for (int h = 0; h < 2; h++) {
            float v = lsum[mi][h];
            v += __shfl_xor_sync(0xffffffffu, v, 1);
            v += __shfl_xor_sync(0xffffffffu, v, 2);
            if ((lane & 3) == 0) {
                int row = m0w + mi * 16 + h * 8 + (lane >> 2);
                smf[row * 4 + (wid & 3)] = v;
            }
        }
    __syncthreads();
    if (tid < 128) {
        float s = smf[tid * 4] + smf[tid * 4 + 1] + smf[tid * 4 + 2] + smf[tid * 4 + 3];
        inv[tid] = 1.0f / s;
    }
    __syncthreads();

    // ---- normalize + split-bf16 context out ----
#pragma unroll
    for (int mi = 0; mi < 4; mi++) {
        const int lr1 = m0w + mi * 16 + (lane >> 2);
        const int lr2 = lr1 + 8;
        const float i1 = inv[lr1], i2 = inv[lr2];
#pragma unroll
        for (int nf = 0; nf < 2; nf++) {
            const int c = (wid & 3) * 16 + nf * 8 + (lane & 3) * 2;
            float* d = acc_o[mi][nf];
            uint32_t hp, lp;
            split_trunc2(d[0] * i1, d[1] * i1, hp, lp);
            size_t idx = (size_t)(q0 + lr1) * E + hoff + c;
            *reinterpret_cast<uint32_t*>(Ch + idx) = hp;
            *reinterpret_cast<uint32_t*>(Cl + idx) = lp;
            split_trunc2(d[2] * i2, d[3] * i2, hp, lp);
            idx = (size_t)(q0 + lr2) * E + hoff + c;
            *reinterpret_cast<uint32_t*>(Ch + idx) = hp;
            *reinterpret_cast<uint32_t*>(Cl + idx) = lp;
        }
    }
}

// ---------------- host side ----------------
extern "C" void kernel_launch(void* const* d_in, const int* in_sizes, int n_in,
                              void* d_out, int out_size)
{
    const float* values = (const float*)d_in[0];
    const float* keys   = (const float*)d_in[1];
    const float* query  = (const float*)d_in[2];
    const float* dist   = (const float*)d_in[3];
    const float* Wv     = (const float*)d_in[4];
    const float* Wk     = (const float*)d_in[5];
    const float* Wq     = (const float*)d_in[6];
    const float* Wo     = (const float*)d_in[7];
    const float* bo     = (const float*)d_in[8];
    float* out = (float*)d_out;

    __nv_bfloat16 *xqh, *xql, *xkh, *xkl, *xvh, *xvl;
    __nv_bfloat16 *wqh, *wql, *wkh, *wkl, *wvh, *wvl, *woh, *wol;
    __nv_bfloat16 *pq, *pk, *pvh, *pvl, *cxh, *cxl, *biasbf;
    cudaGetSymbolAddress((void**)&xqh, g_xqh); cudaGetSymbolAddress((void**)&xql, g_xql);
    cudaGetSymbolAddress((void**)&xkh, g_xkh); cudaGetSymbolAddress((void**)&xkl, g_xkl);
    cudaGetSymbolAddress((void**)&xvh, g_xvh); cudaGetSymbolAddress((void**)&xvl, g_xvl);
    cudaGetSymbolAddress((void**)&wqh, g_wqh); cudaGetSymbolAddress((void**)&wql, g_wql);
    cudaGetSymbolAddress((void**)&wkh, g_wkh); cudaGetSymbolAddress((void**)&wkl, g_wkl);
    cudaGetSymbolAddress((void**)&wvh, g_wvh); cudaGetSymbolAddress((void**)&wvl, g_wvl);
    cudaGetSymbolAddress((void**)&woh, g_woh); cudaGetSymbolAddress((void**)&wol, g_wol);
    cudaGetSymbolAddress((void**)&pq,  g_pq);
    cudaGetSymbolAddress((void**)&pk,  g_pk);
    cudaGetSymbolAddress((void**)&pvh, g_pvh); cudaGetSymbolAddress((void**)&pvl, g_pvl);
    cudaGetSymbolAddress((void**)&cxh, g_cxh); cudaGetSymbolAddress((void**)&cxl, g_cxl);
    cudaGetSymbolAddress((void**)&biasbf, g_biasbf);

    cudaFuncSetAttribute(gemm_tc<0>, cudaFuncAttributeMaxDynamicSharedMemorySize, GEMM_SMEM);
    cudaFuncSetAttribute(gemm_tc<1>, cudaFuncAttributeMaxDynamicSharedMemorySize, GEMM_SMEM);
    cudaFuncSetAttribute(gemm_tc<2>, cudaFuncAttributeMaxDynamicSharedMemorySize, GEMM_SMEM);
    cudaFuncSetAttribute(attn_tc,    cudaFuncAttributeMaxDynamicSharedMemorySize, ATTN_SMEM);

    // launch order matters for ncu (-s 5 -c 1 profiles launch #6 = attn_tc)
    const int nConv = (3 * LE + 4 * EE) / 4 / 256;
    conv_all<<<nConv, 256>>>(query, keys, values, Wq, Wk, Wv, Wo,
                             xqh, xql, xkh, xkl, xvh, xvl,
                             wqh, wql, wkh, wkl, wvh, wvl, woh, wol);
    bias_prep<<<(L * L) / 4 / 256, 256>>>(dist, biasbf);

    dim3 gp(E / 128, L / 128);   // (8, 16)
    gemm_tc<0><<<gp, 256, GEMM_SMEM>>>(xqh, xql, wqh, wql,
                                       pq, nullptr, nullptr, nullptr,
                                       KSCALE, L, E, E);
    gemm_tc<0><<<gp, 256, GEMM_SMEM>>>(xkh, xkl, wkh, wkl,
                                       pk, nullptr, nullptr, nullptr,
                                       1.0f, L, E, E);
    gemm_tc<1><<<gp, 256, GEMM_SMEM>>>(xvh, xvl, wvh, wvl,
                                       pvh, pvl, nullptr, nullptr,
                                       1.0f, L, E, E);

    attn_tc<<<dim3(L / 128, NH), 256, ATTN_SMEM>>>(pq, pk, pvh, pvl,
                                                   biasbf, cxh, cxl);

    gemm_tc<2><<<gp, 256, GEMM_SMEM>>>(cxh, cxl, woh, wol,
                                       nullptr, nullptr, out, bo,
                                       1.0f, L, E, E);
}

// round 6
// speedup vs baseline: 4.6174x; 1.1862x over previous
#include <cuda_runtime.h>
#include <cuda_bf16.h>
#include <cstdint>

// ---------------- problem constants ----------------
constexpr int L  = 2048;
constexpr int E  = 1024;
constexpr int NH = 16;
constexpr int HD = 64;
constexpr float KSCALE = 0.04508422002778011f;   // log2(e)/32

// ---------------- device scratch ----------------
__device__ __nv_bfloat16 g_xqh[L * E];                 // query input (1-term)
__device__ __nv_bfloat16 g_xkh[L * E];                 // keys input (1-term)
__device__ __nv_bfloat16 g_xvh[L * E], g_xvl[L * E];   // values split
__device__ __nv_bfloat16 g_wqh[E * E];                 // Wq (1-term)
__device__ __nv_bfloat16 g_wkh[E * E];                 // Wk (1-term)
__device__ __nv_bfloat16 g_wvh[E * E], g_wvl[E * E];   // Wv split
__device__ __nv_bfloat16 g_woh[E * E], g_wol[E * E];   // Wo split
__device__ __nv_bfloat16 g_pq[L * E];                  // projected Q (scaled, 1-term)
__device__ __nv_bfloat16 g_pk[L * E];                  // projected K (1-term)
__device__ __nv_bfloat16 g_pvh[L * E], g_pvl[L * E];   // projected V split
__device__ __nv_bfloat16 g_cxh[L * E], g_cxl[L * E];   // context split
__device__ __nv_bfloat16 g_biasbf[(size_t)L * L];      // bias * log2e/32, bf16

// ---------------- helpers ----------------
__device__ __forceinline__ uint32_t s2u(const void* p) {
    uint32_t a;
    asm("{ .reg .u64 t; cvta.to.shared.u64 t, %1; cvt.u32.u64 %0, t; }"
        : "=r"(a) : "l"(p));
    return a;
}
__device__ __forceinline__ uint32_t sw128(uint32_t off) {
    return off ^ ((off >> 3) & 0x70);
}
__device__ __forceinline__ float ex2f(float x) {
    float r; asm("ex2.approx.f32 %0, %1;" : "=f"(r) : "f"(x)); return r;
}
__device__ __forceinline__ uint32_t pack_rn(float lo, float hi) {
    uint32_t r;
    asm("cvt.rn.bf16x2.f32 %0, %1, %2;" : "=r"(r) : "f"(hi), "f"(lo));
    return r;
}
// truncation split of a pair: hp = hi16 halves, lp = rn-bf16 of residuals
__device__ __forceinline__ void split_trunc2(float f0, float f1,
                                             uint32_t& hp, uint32_t& lp) {
    uint32_t b0 = __float_as_uint(f0), b1 = __float_as_uint(f1);
    asm("prmt.b32 %0, %1, %2, 0x7632;" : "=r"(hp) : "r"(b0), "r"(b1));
    float l0 = f0 - __uint_as_float(b0 & 0xffff0000u);
    float l1 = f1 - __uint_as_float(b1 & 0xffff0000u);
    lp = pack_rn(l0, l1);
}

#define CP_ASYNC16(dst, src) \
    asm volatile("cp.async.cg.shared.global [%0], [%1], 16;" :: "r"(dst), "l"(src))
#define CP_COMMIT() asm volatile("cp.async.commit_group;" ::: "memory")
#define CP_WAIT1()  asm volatile("cp.async.wait_group 1;" ::: "memory")
#define CP_WAIT0()  asm volatile("cp.async.wait_group 0;" ::: "memory")

#define LDSM4(r0, r1, r2, r3, a) \
    asm volatile("ldmatrix.sync.aligned.m8n8.x4.shared.b16 {%0,%1,%2,%3}, [%4];" \
        : "=r"(r0), "=r"(r1), "=r"(r2), "=r"(r3) : "r"(a))
#define LDSM4T(r0, r1, r2, r3, a) \
    asm volatile("ldmatrix.sync.aligned.m8n8.x4.trans.shared.b16 {%0,%1,%2,%3}, [%4];" \
        : "=r"(r0), "=r"(r1), "=r"(r2), "=r"(r3) : "r"(a))

#define MMA16816(d, a, b) \
    asm volatile("mma.sync.aligned.m16n8k16.row.col.f32.bf16.bf16.f32 " \
        "{%0,%1,%2,%3}, {%4,%5,%6,%7}, {%8,%9}, {%0,%1,%2,%3};" \
        : "+f"((d)[0]), "+f"((d)[1]), "+f"((d)[2]), "+f"((d)[3]) \
        : "r"((a)[0]), "r"((a)[1]), "r"((a)[2]), "r"((a)[3]), \
          "r"((b)[0]), "r"((b)[1]))

// cp.async one [128 x 64] bf16 tile into SW128-swizzled smem (256 threads)
__device__ __forceinline__ void cp_tile(uint32_t dst, const __nv_bfloat16* src,
                                        int ld, int tid) {
#pragma unroll
    for (int i = 0; i < 4; i++) {
        int u   = i * 256 + tid;
        int row = u >> 3;
        int ch  = u & 7;
        uint32_t d = dst + sw128((uint32_t)(row * 128 + ch * 16));
        CP_ASYNC16(d, src + (size_t)row * ld + ch * 8);
    }
}

// ---------------- fused conversion (single launch) ----------------
__device__ __forceinline__ void conv1_at(const float* s, __nv_bfloat16* d, int i) {
    float4 v = *reinterpret_cast<const float4*>(s + i);
    uint2 o = { pack_rn(v.x, v.y), pack_rn(v.z, v.w) };
    *reinterpret_cast<uint2*>(d + i) = o;
}
__device__ __forceinline__ void conv2_at(const float* s, __nv_bfloat16* dh,
                                         __nv_bfloat16* dl, int i) {
    float4 v = *reinterpret_cast<const float4*>(s + i);
    uint32_t h0, l0, h1, l1;
    split_trunc2(v.x, v.y, h0, l0);
    split_trunc2(v.z, v.w, h1, l1);
    uint2 oh = {h0, h1}, ol = {l0, l1};
    *reinterpret_cast<uint2*>(dh + i) = oh;
    *reinterpret_cast<uint2*>(dl + i) = ol;
}

constexpr int LE = L * E, EE = E * E;

__global__ void conv_all(const float* q, const float* k, const float* v,
                         const float* Wq, const float* Wk,
                         const float* Wv, const float* Wo,
                         __nv_bfloat16* xqh, __nv_bfloat16* xkh,
                         __nv_bfloat16* xvh, __nv_bfloat16* xvl,
                         __nv_bfloat16* wqh, __nv_bfloat16* wkh,
                         __nv_bfloat16* wvh, __nv_bfloat16* wvl,
                         __nv_bfloat16* woh, __nv_bfloat16* wol)
{
    int i = (blockIdx.x * blockDim.x + threadIdx.x) * 4;
    if (i < LE) { conv1_at(q, xqh, i); return; }
    i -= LE;
    if (i < LE) { conv1_at(k, xkh, i); return; }
    i -= LE;
    if (i < LE) { conv2_at(v, xvh, xvl, i); return; }
    i -= LE;
    if (i < EE) { conv1_at(Wq, wqh, i); return; }
    i -= EE;
    if (i < EE) { conv1_at(Wk, wkh, i); return; }
    i -= EE;
    if (i < EE) { conv2_at(Wv, wvh, wvl, i); return; }
    i -= EE;
    conv2_at(Wo, woh, wol, i);
}

// ---------------- bias table: bf16( log2e/32 * 1/(d+1) ) ----------------
// launched twice over halves (keeps attn at launch #6 for ncu)
__global__ void bias_prep(const float* __restrict__ d, __nv_bfloat16* __restrict__ b)
{
    int i = (blockIdx.x * blockDim.x + threadIdx.x) * 4;
    float4 v = *reinterpret_cast<const float4*>(d + i);
    float o0 = (v.x == 0.f) ? 0.f : KSCALE / (v.x + 1.f);
    float o1 = (v.y == 0.f) ? 0.f : KSCALE / (v.y + 1.f);
    float o2 = (v.z == 0.f) ? 0.f : KSCALE / (v.z + 1.f);
    float o3 = (v.w == 0.f) ? 0.f : KSCALE / (v.w + 1.f);
    uint2 o = { pack_rn(o0, o1), pack_rn(o2, o3) };
    *reinterpret_cast<uint2*>(b + i) = o;
}

// ---------------- fused 1-term Q+K projection GEMM ----------------
// C = bf16(oscale * (A @ B^T)), 128x128 tile, 2 CTAs/SM (64KB smem, <=128 regs)
constexpr int QK_SMEM = 65536;

__global__ void __launch_bounds__(256, 2)
gemm1_qk(const __nv_bfloat16* __restrict__ A0, const __nv_bfloat16* __restrict__ B0,
         __nv_bfloat16* __restrict__ C0,
         const __nv_bfloat16* __restrict__ A1, const __nv_bfloat16* __restrict__ B1,
         __nv_bfloat16* __restrict__ C1)
{
    const __nv_bfloat16* A = blockIdx.z ? A1 : A0;
    const __nv_bfloat16* B = blockIdx.z ? B1 : B0;
    __nv_bfloat16* C = blockIdx.z ? C1 : C0;
    const float oscale = blockIdx.z ? 1.0f : KSCALE;
    const int M = L, N = E, K = E;

    extern __shared__ char sm[];
    const uint32_t sb = s2u(sm);
    const int tid  = threadIdx.x;
    const int wid  = tid >> 5;
    const int lane = tid & 31;
    const int m0w  = (wid >> 2) * 64;
    const int n0w  = (wid & 3) * 32;
    const int m0 = blockIdx.y * 128;
    const int n0 = blockIdx.x * 128;
    const int sub = lane >> 3, lr = lane & 7;

    float acc[4][4][4];
#pragma unroll
    for (int i = 0; i < 4; i++)
#pragma unroll
        for (int j = 0; j < 4; j++)
#pragma unroll
            for (int k = 0; k < 4; k++) acc[i][j][k] = 0.f;

    const int NC = K / 64;

    {   // prologue chunk 0
        cp_tile(sb,         A + (size_t)m0 * K, K, tid);
        cp_tile(sb + 16384, B + (size_t)n0 * K, K, tid);
        CP_COMMIT();
    }

    for (int kc = 0; kc < NC; kc++) {
        if (kc + 1 < NC) {
            uint32_t base = sb + ((kc + 1) & 1) * 32768;
            const int k0 = (kc + 1) * 64;
            cp_tile(base,         A + (size_t)m0 * K + k0, K, tid);
            cp_tile(base + 16384, B + (size_t)n0 * K + k0, K, tid);
            CP_COMMIT();
            CP_WAIT1();
        } else {
            CP_WAIT0();
        }
        __syncthreads();

        const uint32_t base = sb + (kc & 1) * 32768;
#pragma unroll
        for (int ks = 0; ks < 4; ks++) {
            const int ch = ks * 2 + (sub >> 1);
            uint32_t ah[4][4], bh[4][2];
#pragma unroll
            for (int mi = 0; mi < 4; mi++) {
                int r = m0w + mi * 16 + (sub & 1) * 8 + lr;
                uint32_t off = sw128((uint32_t)(r * 128 + ch * 16));
                LDSM4(ah[mi][0], ah[mi][1], ah[mi][2], ah[mi][3], base + off);
            }
#pragma unroll
            for (int ng = 0; ng < 2; ng++) {
                int r = n0w + ng * 16 + (sub & 1) * 8 + lr;
                uint32_t off = sw128((uint32_t)(r * 128 + ch * 16));
                uint32_t t0, t1, t2, t3;
                LDSM4(t0, t1, t2, t3, base + 16384 + off);
                bh[2*ng][0] = t0; bh[2*ng][1] = t2;
                bh[2*ng+1][0] = t1; bh[2*ng+1][1] = t3;
            }
#pragma unroll
            for (int mi = 0; mi < 4; mi++)
#pragma unroll
                for (int ni = 0; ni < 4; ni++)
                    MMA16816(acc[mi][ni], ah[mi], bh[ni]);
        }
        __syncthreads();
    }

    // epilogue: bf16 out, scaled
#pragma unroll
    for (int mi = 0; mi < 4; mi++) {
        int r1 = m0 + m0w + mi * 16 + (lane >> 2);
        int r2 = r1 + 8;
#pragma unroll
        for (int ni = 0; ni < 4; ni++) {
            int col = n0 + n0w + ni * 8 + (lane & 3) * 2;
            float* d = acc[mi][ni];
            *reinterpret_cast<uint32_t*>(C + (size_t)r1 * N + col) =
                pack_rn(d[0] * oscale, d[1] * oscale);
            *reinterpret_cast<uint32_t*>(C + (size_t)r2 * N + col) =
                pack_rn(d[2] * oscale, d[3] * oscale);
        }
    }
}

// ---------------- 3-term split GEMM: C = A @ B^T via mma.sync ----------------
// OMODE: 1 = split-bf16 out; 2 = fp32 + bias
constexpr int GEMM_SMEM = 131072;

template <int OMODE>
__global__ void __launch_bounds__(256)
gemm_tc(const __nv_bfloat16* __restrict__ Ah, const __nv_bfloat16* __restrict__ Al,
        const __nv_bfloat16* __restrict__ Bh, const __nv_bfloat16* __restrict__ Bl,
        __nv_bfloat16* __restrict__ Ch, __nv_bfloat16* __restrict__ Cl,
        float* __restrict__ Cf, const float* __restrict__ bvec,
        int M, int N, int K)
{
    extern __shared__ char sm[];
    const uint32_t sb = s2u(sm);
    const int tid  = threadIdx.x;
    const int wid  = tid >> 5;
    const int lane = tid & 31;
    const int m0w  = (wid >> 2) * 64;
    const int n0w  = (wid & 3) * 32;
    const int m0 = blockIdx.y * 128;
    const int n0 = blockIdx.x * 128;
    const int sub = lane >> 3, lr = lane & 7;

    float acc[4][4][4];
#pragma unroll
    for (int i = 0; i < 4; i++)
#pragma unroll
        for (int j = 0; j < 4; j++)
#pragma unroll
            for (int k = 0; k < 4; k++) acc[i][j][k] = 0.f;

    const int NC = K / 64;

    {   // prologue chunk 0
        cp_tile(sb,         Ah + (size_t)m0 * K, K, tid);
        cp_tile(sb + 16384, Al + (size_t)m0 * K, K, tid);
        cp_tile(sb + 32768, Bh + (size_t)n0 * K, K, tid);
        cp_tile(sb + 49152, Bl + (size_t)n0 * K, K, tid);
        CP_COMMIT();
    }

    for (int kc = 0; kc < NC; kc++) {
        if (kc + 1 < NC) {
            uint32_t base = sb + ((kc + 1) & 1) * 65536;
            const int k0 = (kc + 1) * 64;
            cp_tile(base,         Ah + (size_t)m0 * K + k0, K, tid);
            cp_tile(base + 16384, Al + (size_t)m0 * K + k0, K, tid);
            cp_tile(base + 32768, Bh + (size_t)n0 * K + k0, K, tid);
            cp_tile(base + 49152, Bl + (size_t)n0 * K + k0, K, tid);
            CP_COMMIT();
            CP_WAIT1();
        } else {
            CP_WAIT0();
        }
        __syncthreads();

        const uint32_t base = sb + (kc & 1) * 65536;
#pragma unroll
        for (int ks = 0; ks < 4; ks++) {
            const int ch = ks * 2 + (sub >> 1);
            uint32_t ah[4][4], al[4][4], bh[4][2], bl[4][2];
#pragma unroll
            for (int mi = 0; mi < 4; mi++) {
                int r = m0w + mi * 16 + (sub & 1) * 8 + lr;
                uint32_t off = sw128((uint32_t)(r * 128 + ch * 16));
                LDSM4(ah[mi][0], ah[mi][1], ah[mi][2], ah[mi][3], base + off);
                LDSM4(al[mi][0], al[mi][1], al[mi][2], al[mi][3], base + 16384 + off);
            }
#pragma unroll
            for (int ng = 0; ng < 2; ng++) {
                int r = n0w + ng * 16 + (sub & 1) * 8 + lr;
                uint32_t off = sw128((uint32_t)(r * 128 + ch * 16));
                uint32_t t0, t1, t2, t3;
                LDSM4(t0, t1, t2, t3, base + 32768 + off);
                bh[2*ng][0] = t0; bh[2*ng][1] = t2;
                bh[2*ng+1][0] = t1; bh[2*ng+1][1] = t3;
                LDSM4(t0, t1, t2, t3, base + 49152 + off);
                bl[2*ng][0] = t0; bl[2*ng][1] = t2;
                bl[2*ng+1][0] = t1; bl[2*ng+1][1] = t3;
            }
#pragma unroll
            for (int mi = 0; mi < 4; mi++)
#pragma unroll
                for (int ni = 0; ni < 4; ni++) {
                    MMA16816(acc[mi][ni], ah[mi], bh[ni]);
                    MMA16816(acc[mi][ni], ah[mi], bl[ni]);
                    MMA16816(acc[mi][ni], al[mi], bh[ni]);
                }
        }
        __syncthreads();
    }

    // epilogue
#pragma unroll
    for (int mi = 0; mi < 4; mi++) {
        int r1 = m0 + m0w + mi * 16 + (lane >> 2);
        int r2 = r1 + 8;
#pragma unroll
        for (int ni = 0; ni < 4; ni++) {
            int col = n0 + n0w + ni * 8 + (lane & 3) * 2;
            float* d = acc[mi][ni];
            if (OMODE == 1) {
                uint32_t hp, lp;
                split_trunc2(d[0], d[1], hp, lp);
                *reinterpret_cast<uint32_t*>(Ch + (size_t)r1 * N + col) = hp;
                *reinterpret_cast<uint32_t*>(Cl + (size_t)r1 * N + col) = lp;
                split_trunc2(d[2], d[3], hp, lp);
                *reinterpret_cast<uint32_t*>(Ch + (size_t)r2 * N + col) = hp;
                *reinterpret_cast<uint32_t*>(Cl + (size_t)r2 * N + col) = lp;
            } else {
                float2 bv = *reinterpret_cast<const float2*>(bvec + col);
                float2 o1 = {d[0] + bv.x, d[1] + bv.y};
                float2 o2 = {d[2] + bv.x, d[3] + bv.y};
                *reinterpret_cast<float2*>(Cf + (size_t)r1 * N + col) = o1;
                *reinterpret_cast<float2*>(Cf + (size_t)r2 * N + col) = o2;
            }
        }
    }
}

// ---------------- attention ----------------
// CTA = 128 queries x 1 head, 256 threads (8 warps, 2x4).
// Q pre-scaled by log2e/32 (1-term); K 1-term; p = ex2(S + biasbf); PV 3-term.
constexpr uint32_t AQ   = 0;
constexpr uint32_t AKV0 = 16384;
constexpr uint32_t AKV1 = 65536;
constexpr uint32_t AP   = 114688;
constexpr uint32_t APL  = 147456;
constexpr int ATTN_SMEM = 180224;

__global__ void __launch_bounds__(256, 1)
attn_tc(const __nv_bfloat16* __restrict__ Q,
        const __nv_bfloat16* __restrict__ Kp,
        const __nv_bfloat16* __restrict__ Vh, const __nv_bfloat16* __restrict__ Vl,
        const __nv_bfloat16* __restrict__ biasbf,
        __nv_bfloat16* __restrict__ Ch, __nv_bfloat16* __restrict__ Cl)
{
    extern __shared__ char sm[];
    const uint32_t sb = s2u(sm);
    const int tid  = threadIdx.x;
    const int wid  = tid >> 5;
    const int lane = tid & 31;
    const int m0w  = (wid >> 2) * 64;
    const int n0w  = (wid & 3) * 32;
    const int q0   = blockIdx.x * 128;
    const int hoff = blockIdx.y * HD;
    const int sub = lane >> 3, lr = lane & 7;

    // prologue: Q + KV0 in one group
    cp_tile(sb + AQ, Q + (size_t)q0 * E + hoff, E, tid);
    cp_tile(sb + AKV0,         Kp + hoff, E, tid);
    cp_tile(sb + AKV0 + 16384, Vh + hoff, E, tid);
    cp_tile(sb + AKV0 + 32768, Vl + hoff, E, tid);
    CP_COMMIT();

    float acc_o[4][2][4];
#pragma unroll
    for (int i = 0; i < 4; i++)
#pragma unroll
        for (int j = 0; j < 2; j++)
#pragma unroll
            for (int k = 0; k < 4; k++) acc_o[i][j][k] = 0.f;
    float lsum[4][2];
#pragma unroll
    for (int i = 0; i < 4; i++) { lsum[i][0] = 0.f; lsum[i][1] = 0.f; }

    for (int kt = 0; kt < L / 128; kt++) {
        const int kb = kt * 128;
        if (kt + 1 < L / 128) {
            uint32_t base = sb + (((kt + 1) & 1) ? AKV1 : AKV0);
            const size_t ro = (size_t)(kb + 128) * E + hoff;
            cp_tile(base,         Kp + ro, E, tid);
            cp_tile(base + 16384, Vh + ro, E, tid);
            cp_tile(base + 32768, Vl + ro, E, tid);
            CP_COMMIT();
            CP_WAIT1();
        } else {
            CP_WAIT0();
        }
        __syncthreads();

        const uint32_t bkv = sb + ((kt & 1) ? AKV1 : AKV0);

        // ---- S = Q @ K^T (1-term bf16) ----
        float acc_s[4][4][4];
#pragma unroll
        for (int i = 0; i < 4; i++)
#pragma unroll
            for (int j = 0; j < 4; j++)
#pragma unroll
                for (int k = 0; k < 4; k++) acc_s[i][j][k] = 0.f;

#pragma unroll
        for (int ks = 0; ks < 4; ks++) {
            const int ch = ks * 2 + (sub >> 1);
            uint32_t qa[4][4], bh[4][2];
#pragma unroll
            for (int mi = 0; mi < 4; mi++) {
                int r = m0w + mi * 16 + (sub & 1) * 8 + lr;
                uint32_t off = sw128((uint32_t)(r * 128 + ch * 16));
                LDSM4(qa[mi][0], qa[mi][1], qa[mi][2], qa[mi][3], sb + AQ + off);
            }
#pragma unroll
            for (int ng = 0; ng < 2; ng++) {
                int r = n0w + ng * 16 + (sub & 1) * 8 + lr;
                uint32_t off = sw128((uint32_t)(r * 128 + ch * 16));
                uint32_t t0, t1, t2, t3;
                LDSM4(t0, t1, t2, t3, bkv + off);
                bh[2*ng][0] = t0; bh[2*ng][1] = t2;
                bh[2*ng+1][0] = t1; bh[2*ng+1][1] = t3;
            }
#pragma unroll
            for (int mi = 0; mi < 4; mi++)
#pragma unroll
                for (int ni = 0; ni < 4; ni++)
                    MMA16816(acc_s[mi][ni], qa[mi], bh[ni]);
        }

        // ---- p = ex2(S + bias); store split P ----
#pragma unroll
        for (int mi = 0; mi < 4; mi++) {
            const int lr1 = m0w + mi * 16 + (lane >> 2);
            const int lr2 = lr1 + 8;
            const uint32_t* bp1 = reinterpret_cast<const uint32_t*>(
                biasbf + (size_t)(q0 + lr1) * L + kb);
            const uint32_t* bp2 = reinterpret_cast<const uint32_t*>(
                biasbf + (size_t)(q0 + lr2) * L + kb);
#pragma unroll
            for (int ni = 0; ni < 4; ni++) {
                const int lc = n0w + ni * 8 + (lane & 3) * 2;
                uint32_t pk1 = bp1[lc >> 1];
                uint32_t pk2 = bp2[lc >> 1];
                float* d = acc_s[mi][ni];
                float p0 = ex2f(d[0] + __uint_as_float(pk1 << 16));
                float p1 = ex2f(d[1] + __uint_as_float(pk1 & 0xffff0000u));
                float p2 = ex2f(d[2] + __uint_as_float(pk2 << 16));
                float p3 = ex2f(d[3] + __uint_as_float(pk2 & 0xffff0000u));
                lsum[mi][0] += p0 + p1;
                lsum[mi][1] += p2 + p3;
                uint32_t hp, lp;
                const int chn = lc >> 3, cb = (lc & 7) * 2;
                split_trunc2(p0, p1, hp, lp);
                uint32_t a1 = lr1 * 256 + (((uint32_t)(chn ^ (lr1 & 7))) << 4) + cb;
                *reinterpret_cast<uint32_t*>(sm + AP  + a1) = hp;
                *reinterpret_cast<uint32_t*>(sm + APL + a1) = lp;
                split_trunc2(p2, p3, hp, lp);
                uint32_t a2 = lr2 * 256 + (((uint32_t)(chn ^ (lr2 & 7))) << 4) + cb;
                *reinterpret_cast<uint32_t*>(sm + AP  + a2) = hp;
                *reinterpret_cast<uint32_t*>(sm + APL + a2) = lp;
            }
        }
        __syncthreads();

        // ---- O += P @ V (3-term) ----
#pragma unroll
        for (int ks = 0; ks < 8; ks++) {
            const int ch = ks * 2 + (sub >> 1);
            uint32_t ah[4][4], al[4][4], bh[2][2], bl[2][2];
#pragma unroll
            for (int mi = 0; mi < 4; mi++) {
                int r = m0w + mi * 16 + (sub & 1) * 8 + lr;
                uint32_t off = (uint32_t)(r * 256) + (((uint32_t)(ch ^ (r & 7))) << 4);
                LDSM4(ah[mi][0], ah[mi][1], ah[mi][2], ah[mi][3], sb + AP + off);
                LDSM4(al[mi][0], al[mi][1], al[mi][2], al[mi][3], sb + APL + off);
            }
            {
                int rv = ks * 16 + (sub >> 1) * 8 + lr;
                int cv = (wid & 3) * 2 + (sub & 1);
                uint32_t off = sw128((uint32_t)(rv * 128 + cv * 16));
                uint32_t t0, t1, t2, t3;
                LDSM4T(t0, t1, t2, t3, bkv + 16384 + off);
                bh[0][0] = t0; bh[0][1] = t2; bh[1][0] = t1; bh[1][1] = t3;
                LDSM4T(t0, t1, t2, t3, bkv + 32768 + off);
                bl[0][0] = t0; bl[0][1] = t2; bl[1][0] = t1; bl[1][1] = t3;
            }
#pragma unroll
            for (int mi = 0; mi < 4; mi++)
#pragma unroll
                for (int nf = 0; nf < 2; nf++) {
                    MMA16816(acc_o[mi][nf], ah[mi], bh[nf]);
                    MMA16816(acc_o[mi][nf], ah[mi], bl[nf]);
                    MMA16816(acc_o[mi][nf], al[mi], bh[nf]);
                }
        }
        __syncthreads();
    }

    // ---- row-sum reduction (reuse P smem) ----
    float* smf = reinterpret_cast<float*>(sm + AP);
    float* inv = smf + 512;
#pragma unroll
    for (int mi = 0; mi < 4; mi++)
#pragma unroll
        for (int h = 0; h < 2; h++) {
            float v = lsum[mi][h];
            v += __shfl_xor_sync(0xffffffffu, v, 1);
            v += __shfl_xor_sync(0xffffffffu, v, 2);
            if ((lane & 3) == 0) {
                int row = m0w + mi * 16 + h * 8 + (lane >> 2);
                smf[row * 4 + (wid & 3)] = v;
            }
        }
    __syncthreads();
    if (tid < 128) {
        float s = smf[tid * 4] + smf[tid * 4 + 1] + smf[tid * 4 + 2] + smf[tid * 4 + 3];
        inv[tid] = 1.0f / s;
    }
    __syncthreads();

    // ---- normalize + split-bf16 context out ----
#pragma unroll
    for (int mi = 0; mi < 4; mi++) {
        const int lr1 = m0w + mi * 16 + (lane >> 2);
        const int lr2 = lr1 + 8;
        const float i1 = inv[lr1], i2 = inv[lr2];
#pragma unroll
        for (int nf = 0; nf < 2; nf++) {
            const int c = (wid & 3) * 16 + nf * 8 + (lane & 3) * 2;
            float* d = acc_o[mi][nf];
            uint32_t hp, lp;
            split_trunc2(d[0] * i1, d[1] * i1, hp, lp);
            size_t idx = (size_t)(q0 + lr1) * E + hoff + c;
            *reinterpret_cast<uint32_t*>(Ch + idx) = hp;
            *reinterpret_cast<uint32_t*>(Cl + idx) = lp;
            split_trunc2(d[2] * i2, d[3] * i2, hp, lp);
            idx = (size_t)(q0 + lr2) * E + hoff + c;
            *reinterpret_cast<uint32_t*>(Ch + idx) = hp;
            *reinterpret_cast<uint32_t*>(Cl + idx) = lp;
        }
    }
}

// ---------------- host side ----------------
extern "C" void kernel_launch(void* const* d_in, const int* in_sizes, int n_in,
                              void* d_out, int out_size)
{
    const float* values = (const float*)d_in[0];
    const float* keys   = (const float*)d_in[1];
    const float* query  = (const float*)d_in[2];
    const float* dist   = (const float*)d_in[3];
    const float* Wv     = (const float*)d_in[4];
    const float* Wk     = (const float*)d_in[5];
    const float* Wq     = (const float*)d_in[6];
    const float* Wo     = (const float*)d_in[7];
    const float* bo     = (const float*)d_in[8];
    float* out = (float*)d_out;

    __nv_bfloat16 *xqh, *xkh, *xvh, *xvl;
    __nv_bfloat16 *wqh, *wkh, *wvh, *wvl, *woh, *wol;
    __nv_bfloat16 *pq, *pk, *pvh, *pvl, *cxh, *cxl, *biasbf;
    cudaGetSymbolAddress((void**)&xqh, g_xqh);
    cudaGetSymbolAddress((void**)&xkh, g_xkh);
    cudaGetSymbolAddress((void**)&xvh, g_xvh); cudaGetSymbolAddress((void**)&xvl, g_xvl);
    cudaGetSymbolAddress((void**)&wqh, g_wqh);
    cudaGetSymbolAddress((void**)&wkh, g_wkh);
    cudaGetSymbolAddress((void**)&wvh, g_wvh); cudaGetSymbolAddress((void**)&wvl, g_wvl);
    cudaGetSymbolAddress((void**)&woh, g_woh); cudaGetSymbolAddress((void**)&wol, g_wol);
    cudaGetSymbolAddress((void**)&pq,  g_pq);
    cudaGetSymbolAddress((void**)&pk,  g_pk);
    cudaGetSymbolAddress((void**)&pvh, g_pvh); cudaGetSymbolAddress((void**)&pvl, g_pvl);
    cudaGetSymbolAddress((void**)&cxh, g_cxh); cudaGetSymbolAddress((void**)&cxl, g_cxl);
    cudaGetSymbolAddress((void**)&biasbf, g_biasbf);

    cudaFuncSetAttribute(gemm1_qk,   cudaFuncAttributeMaxDynamicSharedMemorySize, QK_SMEM);
    cudaFuncSetAttribute(gemm_tc<1>, cudaFuncAttributeMaxDynamicSharedMemorySize, GEMM_SMEM);
    cudaFuncSetAttribute(gemm_tc<2>, cudaFuncAttributeMaxDynamicSharedMemorySize, GEMM_SMEM);
    cudaFuncSetAttribute(attn_tc,    cudaFuncAttributeMaxDynamicSharedMemorySize, ATTN_SMEM);

    // launches: 1 conv, 2-3 bias halves, 4 QK gemm, 5 V gemm, 6 attn, 7 O gemm
    const int nConv = (3 * LE + 4 * EE) / 4 / 256;
    conv_all<<<nConv, 256>>>(query, keys, values, Wq, Wk, Wv, Wo,
                             xqh, xkh, xvh, xvl, wqh, wkh, wvh, wvl, woh, wol);
    const int nBias = (L * L) / 4 / 256;     // 4096 blocks total
    bias_prep<<<nBias / 2, 256>>>(dist, biasbf);
    bias_prep<<<nBias / 2, 256>>>(dist + (size_t)L * L / 2,
                                  biasbf + (size_t)L * L / 2);

    dim3 gqk(E / 128, L / 128, 2);   // (8, 16, 2) = 256 CTAs
    gemm1_qk<<<gqk, 256, QK_SMEM>>>(xqh, wqh, pq, xkh, wkh, pk);

    dim3 gp(E / 128, L / 128);       // (8, 16)
    gemm_tc<1><<<gp, 256, GEMM_SMEM>>>(xvh, xvl, wvh, wvl,
                                       pvh, pvl, nullptr, nullptr, L, E, E);

    attn_tc<<<dim3(L / 128, NH), 256, ATTN_SMEM>>>(pq, pk, pvh, pvl,
                                                   biasbf, cxh, cxl);

    gemm_tc<2><<<gp, 256, GEMM_SMEM>>>(cxh, cxl, woh, wol,
                                       nullptr, nullptr, out, bo, L, E, E);
}

// round 7
// speedup vs baseline: 5.1202x; 1.1089x over previous
#include <cuda_runtime.h>
#include <cuda_fp16.h>
#include <cuda_bf16.h>
#include <cstdint>

// ---------------- problem constants ----------------
constexpr int L  = 2048;
constexpr int E  = 1024;
constexpr int NH = 16;
constexpr int HD = 64;
constexpr float KSCALE = 0.04508422002778011f;   // log2(e)/32

// ---------------- device scratch ----------------
__device__ __half g_xqh[L * E];                 // query input (1-term)
__device__ __half g_xkh[L * E];                 // keys input (1-term)
__device__ __half g_xvh[L * E], g_xvl[L * E];   // values split
__device__ __half g_wqh[E * E];                 // Wq (1-term)
__device__ __half g_wkh[E * E];                 // Wk (1-term)
__device__ __half g_wvh[E * E], g_wvl[E * E];   // Wv split
__device__ __half g_woh[E * E], g_wol[E * E];   // Wo split
__device__ __half g_pq[L * E];                  // projected Q (scaled, 1-term)
__device__ __half g_pk[L * E];                  // projected K (1-term)
__device__ __half g_pvh[L * E], g_pvl[L * E];   // projected V split
__device__ __half g_cxh[L * E], g_cxl[L * E];   // context split
__device__ __nv_bfloat16 g_biasbf[(size_t)L * L];  // bias * log2e/32, bf16

// ---------------- helpers ----------------
__device__ __forceinline__ uint32_t s2u(const void* p) {
    uint32_t a;
    asm("{ .reg .u64 t; cvta.to.shared.u64 t, %1; cvt.u32.u64 %0, t; }"
        : "=r"(a) : "l"(p));
    return a;
}
__device__ __forceinline__ uint32_t sw128(uint32_t off) {
    return off ^ ((off >> 3) & 0x70);
}
__device__ __forceinline__ float ex2f(float x) {
    float r; asm("ex2.approx.f32 %0, %1;" : "=f"(r) : "f"(x)); return r;
}
// pack two floats as f16x2, lo in low half
__device__ __forceinline__ uint32_t pack_h2(float lo, float hi) {
    uint32_t r;
    asm("cvt.rn.f16x2.f32 %0, %1, %2;" : "=r"(r) : "f"(hi), "f"(lo));
    return r;
}
__device__ __forceinline__ uint32_t pack_bf2(float lo, float hi) {
    uint32_t r;
    asm("cvt.rn.bf16x2.f32 %0, %1, %2;" : "=r"(r) : "f"(hi), "f"(lo));
    return r;
}
// fp16 split of a pair: hp = rn-f16 of values, lp = rn-f16 of residuals
__device__ __forceinline__ void split_h2(float f0, float f1,
                                         uint32_t& hp, uint32_t& lp) {
    hp = pack_h2(f0, f1);
    __half2 h = *reinterpret_cast<__half2*>(&hp);
    float2 hf = __half22float2(h);
    lp = pack_h2(f0 - hf.x, f1 - hf.y);
}

#define CP_ASYNC16(dst, src) \
    asm volatile("cp.async.cg.shared.global [%0], [%1], 16;" :: "r"(dst), "l"(src))
#define CP_COMMIT() asm volatile("cp.async.commit_group;" ::: "memory")
#define CP_WAIT1()  asm volatile("cp.async.wait_group 1;" ::: "memory")
#define CP_WAIT0()  asm volatile("cp.async.wait_group 0;" ::: "memory")

#define LDSM4(r0, r1, r2, r3, a) \
    asm volatile("ldmatrix.sync.aligned.m8n8.x4.shared.b16 {%0,%1,%2,%3}, [%4];" \
        : "=r"(r0), "=r"(r1), "=r"(r2), "=r"(r3) : "r"(a))
#define LDSM4T(r0, r1, r2, r3, a) \
    asm volatile("ldmatrix.sync.aligned.m8n8.x4.trans.shared.b16 {%0,%1,%2,%3}, [%4];" \
        : "=r"(r0), "=r"(r1), "=r"(r2), "=r"(r3) : "r"(a))

#define MMA16816(d, a, b) \
    asm volatile("mma.sync.aligned.m16n8k16.row.col.f32.f16.f16.f32 " \
        "{%0,%1,%2,%3}, {%4,%5,%6,%7}, {%8,%9}, {%0,%1,%2,%3};" \
        : "+f"((d)[0]), "+f"((d)[1]), "+f"((d)[2]), "+f"((d)[3]) \
        : "r"((a)[0]), "r"((a)[1]), "r"((a)[2]), "r"((a)[3]), \
          "r"((b)[0]), "r"((b)[1]))

// cp.async one [128 x 64] f16 tile into SW128-swizzled smem (256 threads)
__device__ __forceinline__ void cp_tile(uint32_t dst, const __half* src,
                                        int ld, int tid) {
#pragma unroll
    for (int i = 0; i < 4; i++) {
        int u   = i * 256 + tid;
        int row = u >> 3;
        int ch  = u & 7;
        uint32_t d = dst + sw128((uint32_t)(row * 128 + ch * 16));
        CP_ASYNC16(d, src + (size_t)row * ld + ch * 8);
    }
}

// ---------------- fused conversion (single launch) ----------------
__device__ __forceinline__ void conv1_at(const float* s, __half* d, int i) {
    float4 v = *reinterpret_cast<const float4*>(s + i);
    uint2 o = { pack_h2(v.x, v.y), pack_h2(v.z, v.w) };
    *reinterpret_cast<uint2*>(d + i) = o;
}
__device__ __forceinline__ void conv2_at(const float* s, __half* dh,
                                         __half* dl, int i) {
    float4 v = *reinterpret_cast<const float4*>(s + i);
    uint32_t h0, l0, h1, l1;
    split_h2(v.x, v.y, h0, l0);
    split_h2(v.z, v.w, h1, l1);
    uint2 oh = {h0, h1}, ol = {l0, l1};
    *reinterpret_cast<uint2*>(dh + i) = oh;
    *reinterpret_cast<uint2*>(dl + i) = ol;
}

constexpr int LE = L * E, EE = E * E;

__global__ void conv_all(const float* q, const float* k, const float* v,
                         const float* Wq, const float* Wk,
                         const float* Wv, const float* Wo,
                         __half* xqh, __half* xkh,
                         __half* xvh, __half* xvl,
                         __half* wqh, __half* wkh,
                         __half* wvh, __half* wvl,
                         __half* woh, __half* wol)
{
    int i = (blockIdx.x * blockDim.x + threadIdx.x) * 4;
    if (i < LE) { conv1_at(q, xqh, i); return; }
    i -= LE;
    if (i < LE) { conv1_at(k, xkh, i); return; }
    i -= LE;
    if (i < LE) { conv2_at(v, xvh, xvl, i); return; }
    i -= LE;
    if (i < EE) { conv1_at(Wq, wqh, i); return; }
    i -= EE;
    if (i < EE) { conv1_at(Wk, wkh, i); return; }
    i -= EE;
    if (i < EE) { conv2_at(Wv, wvh, wvl, i); return; }
    i -= EE;
    conv2_at(Wo, woh, wol, i);
}

// ---------------- bias table: bf16( log2e/32 * 1/(d+1) ) ----------------
__global__ void bias_prep(const float* __restrict__ d, __nv_bfloat16* __restrict__ b)
{
    int i = (blockIdx.x * blockDim.x + threadIdx.x) * 4;
    float4 v = *reinterpret_cast<const float4*>(d + i);
    float o0 = (v.x == 0.f) ? 0.f : KSCALE / (v.x + 1.f);
    float o1 = (v.y == 0.f) ? 0.f : KSCALE / (v.y + 1.f);
    float o2 = (v.z == 0.f) ? 0.f : KSCALE / (v.z + 1.f);
    float o3 = (v.w == 0.f) ? 0.f : KSCALE / (v.w + 1.f);
    uint2 o = { pack_bf2(o0, o1), pack_bf2(o2, o3) };
    *reinterpret_cast<uint2*>(b + i) = o;
}

// ---------------- fused 1-term Q+K projection GEMM ----------------
constexpr int QK_SMEM = 65536;

__global__ void __launch_bounds__(256, 2)
gemm1_qk(const __half* __restrict__ A0, const __half* __restrict__ B0,
         __half* __restrict__ C0,
         const __half* __restrict__ A1, const __half* __restrict__ B1,
         __half* __restrict__ C1)
{
    const __half* A = blockIdx.z ? A1 : A0;
    const __half* B = blockIdx.z ? B1 : B0;
    __half* C = blockIdx.z ? C1 : C0;
    const float oscale = blockIdx.z ? 1.0f : KSCALE;
    const int N = E, K = E;

    extern __shared__ char sm[];
    const uint32_t sb = s2u(sm);
    const int tid  = threadIdx.x;
    const int wid  = tid >> 5;
    const int lane = tid & 31;
    const int m0w  = (wid >> 2) * 64;
    const int n0w  = (wid & 3) * 32;
    const int m0 = blockIdx.y * 128;
    const int n0 = blockIdx.x * 128;
    const int sub = lane >> 3, lr = lane & 7;

    float acc[4][4][4];
#pragma unroll
    for (int i = 0; i < 4; i++)
#pragma unroll
        for (int j = 0; j < 4; j++)
#pragma unroll
            for (int k = 0; k < 4; k++) acc[i][j][k] = 0.f;

    const int NC = K / 64;

    {   // prologue chunk 0
        cp_tile(sb,         A + (size_t)m0 * K, K, tid);
        cp_tile(sb + 16384, B + (size_t)n0 * K, K, tid);
        CP_COMMIT();
    }

    for (int kc = 0; kc < NC; kc++) {
        if (kc + 1 < NC) {
            uint32_t base = sb + ((kc + 1) & 1) * 32768;
            const int k0 = (kc + 1) * 64;
            cp_tile(base,         A + (size_t)m0 * K + k0, K, tid);
            cp_tile(base + 16384, B + (size_t)n0 * K + k0, K, tid);
            CP_COMMIT();
            CP_WAIT1();
        } else {
            CP_WAIT0();
        }
        __syncthreads();

        const uint32_t base = sb + (kc & 1) * 32768;
#pragma unroll
        for (int ks = 0; ks < 4; ks++) {
            const int ch = ks * 2 + (sub >> 1);
            uint32_t ah[4][4], bh[4][2];
#pragma unroll
            for (int mi = 0; mi < 4; mi++) {
                int r = m0w + mi * 16 + (sub & 1) * 8 + lr;
                uint32_t off = sw128((uint32_t)(r * 128 + ch * 16));
                LDSM4(ah[mi][0], ah[mi][1], ah[mi][2], ah[mi][3], base + off);
            }
#pragma unroll
            for (int ng = 0; ng < 2; ng++) {
                int r = n0w + ng * 16 + (sub & 1) * 8 + lr;
                uint32_t off = sw128((uint32_t)(r * 128 + ch * 16));
                uint32_t t0, t1, t2, t3;
                LDSM4(t0, t1, t2, t3, base + 16384 + off);
                bh[2*ng][0] = t0; bh[2*ng][1] = t2;
                bh[2*ng+1][0] = t1; bh[2*ng+1][1] = t3;
            }
#pragma unroll
            for (int mi = 0; mi < 4; mi++)
#pragma unroll
                for (int ni = 0; ni < 4; ni++)
                    MMA16816(acc[mi][ni], ah[mi], bh[ni]);
        }
        __syncthreads();
    }

    // epilogue: f16 out, scaled
#pragma unroll
    for (int mi = 0; mi < 4; mi++) {
        int r1 = m0 + m0w + mi * 16 + (lane >> 2);
        int r2 = r1 + 8;
#pragma unroll
        for (int ni = 0; ni < 4; ni++) {
            int col = n0 + n0w + ni * 8 + (lane & 3) * 2;
            float* d = acc[mi][ni];
            *reinterpret_cast<uint32_t*>(C + (size_t)r1 * N + col) =
                pack_h2(d[0] * oscale, d[1] * oscale);
            *reinterpret_cast<uint32_t*>(C + (size_t)r2 * N + col) =
                pack_h2(d[2] * oscale, d[3] * oscale);
        }
    }
}

// ---------------- 3-term split GEMM: C = A @ B^T ----------------
// OMODE: 1 = split-f16 out; 2 = fp32 + bias
constexpr int GEMM_SMEM = 131072;

template <int OMODE>
__global__ void __launch_bounds__(256)
gemm_tc(const __half* __restrict__ Ah, const __half* __restrict__ Al,
        const __half* __restrict__ Bh, const __half* __restrict__ Bl,
        __half* __restrict__ Ch, __half* __restrict__ Cl,
        float* __restrict__ Cf, const float* __restrict__ bvec,
        int M, int N, int K)
{
    extern __shared__ char sm[];
    const uint32_t sb = s2u(sm);
    const int tid  = threadIdx.x;
    const int wid  = tid >> 5;
    const int lane = tid & 31;
    const int m0w  = (wid >> 2) * 64;
    const int n0w  = (wid & 3) * 32;
    const int m0 = blockIdx.y * 128;
    const int n0 = blockIdx.x * 128;
    const int sub = lane >> 3, lr = lane & 7;

    float acc[4][4][4];
#pragma unroll
    for (int i = 0; i < 4; i++)
#pragma unroll
        for (int j = 0; j < 4; j++)
#pragma unroll
            for (int k = 0; k < 4; k++) acc[i][j][k] = 0.f;

    const int NC = K / 64;

    {   // prologue chunk 0
        cp_tile(sb,         Ah + (size_t)m0 * K, K, tid);
        cp_tile(sb + 16384, Al + (size_t)m0 * K, K, tid);
        cp_tile(sb + 32768, Bh + (size_t)n0 * K, K, tid);
        cp_tile(sb + 49152, Bl + (size_t)n0 * K, K, tid);
        CP_COMMIT();
    }

    for (int kc = 0; kc < NC; kc++) {
        if (kc + 1 < NC) {
            uint32_t base = sb + ((kc + 1) & 1) * 65536;
            const int k0 = (kc + 1) * 64;
            cp_tile(base,         Ah + (size_t)m0 * K + k0, K, tid);
            cp_tile(base + 16384, Al + (size_t)m0 * K + k0, K, tid);
            cp_tile(base + 32768, Bh + (size_t)n0 * K + k0, K, tid);
            cp_tile(base + 49152, Bl + (size_t)n0 * K + k0, K, tid);
            CP_COMMIT();
            CP_WAIT1();
        } else {
            CP_WAIT0();
        }
        __syncthreads();

        const uint32_t base = sb + (kc & 1) * 65536;
#pragma unroll
        for (int ks = 0; ks < 4; ks++) {
            const int ch = ks * 2 + (sub >> 1);
            uint32_t ah[4][4], al[4][4], bh[4][2], bl[4][2];
#pragma unroll
            for (int mi = 0; mi < 4; mi++) {
                int r = m0w + mi * 16 + (sub & 1) * 8 + lr;
                uint32_t off = sw128((uint32_t)(r * 128 + ch * 16));
                LDSM4(ah[mi][0], ah[mi][1], ah[mi][2], ah[mi][3], base + off);
                LDSM4(al[mi][0], al[mi][1], al[mi][2], al[mi][3], base + 16384 + off);
            }
#pragma unroll
            for (int ng = 0; ng < 2; ng++) {
                int r = n0w + ng * 16 + (sub & 1) * 8 + lr;
                uint32_t off = sw128((uint32_t)(r * 128 + ch * 16));
                uint32_t t0, t1, t2, t3;
                LDSM4(t0, t1, t2, t3, base + 32768 + off);
                bh[2*ng][0] = t0; bh[2*ng][1] = t2;
                bh[2*ng+1][0] = t1; bh[2*ng+1][1] = t3;
                LDSM4(t0, t1, t2, t3, base + 49152 + off);
                bl[2*ng][0] = t0; bl[2*ng][1] = t2;
                bl[2*ng+1][0] = t1; bl[2*ng+1][1] = t3;
            }
#pragma unroll
            for (int mi = 0; mi < 4; mi++)
#pragma unroll
                for (int ni = 0; ni < 4; ni++) {
                    MMA16816(acc[mi][ni], ah[mi], bh[ni]);
                    MMA16816(acc[mi][ni], ah[mi], bl[ni]);
                    MMA16816(acc[mi][ni], al[mi], bh[ni]);
                }
        }
        __syncthreads();
    }

    // epilogue
#pragma unroll
    for (int mi = 0; mi < 4; mi++) {
        int r1 = m0 + m0w + mi * 16 + (lane >> 2);
        int r2 = r1 + 8;
#pragma unroll
        for (int ni = 0; ni < 4; ni++) {
            int col = n0 + n0w + ni * 8 + (lane & 3) * 2;
            float* d = acc[mi][ni];
            if (OMODE == 1) {
                uint32_t hp, lp;
                split_h2(d[0], d[1], hp, lp);
                *reinterpret_cast<uint32_t*>(Ch + (size_t)r1 * N + col) = hp;
                *reinterpret_cast<uint32_t*>(Cl + (size_t)r1 * N + col) = lp;
                split_h2(d[2], d[3], hp, lp);
                *reinterpret_cast<uint32_t*>(Ch + (size_t)r2 * N + col) = hp;
                *reinterpret_cast<uint32_t*>(Cl + (size_t)r2 * N + col) = lp;
            } else {
                float2 bv = *reinterpret_cast<const float2*>(bvec + col);
                float2 o1 = {d[0] + bv.x, d[1] + bv.y};
                float2 o2 = {d[2] + bv.x, d[3] + bv.y};
                *reinterpret_cast<float2*>(Cf + (size_t)r1 * N + col) = o1;
                *reinterpret_cast<float2*>(Cf + (size_t)r2 * N + col) = o2;
            }
        }
    }
}

// ---------------- attention ----------------
// CTA = 128 queries x 1 head, 256 threads (8 warps, 2x4).
// Q pre-scaled (1-term f16); K 1-term; p = ex2(S + biasbf) stored 1-term f16;
// PV = P@Vh + P@Vl (V split f16).
constexpr uint32_t AQ   = 0;
constexpr uint32_t AKV0 = 16384;
constexpr uint32_t AKV1 = 65536;
constexpr uint32_t AP   = 114688;
constexpr int ATTN_SMEM = 147456;

__global__ void __launch_bounds__(256, 1)
attn_tc(const __half* __restrict__ Q,
        const __half* __restrict__ Kp,
        const __half* __restrict__ Vh, const __half* __restrict__ Vl,
        const __nv_bfloat16* __restrict__ biasbf,
        __half* __restrict__ Ch, __half* __restrict__ Cl)
{
    extern __shared__ char sm[];
    const uint32_t sb = s2u(sm);
    const int tid  = threadIdx.x;
    const int wid  = tid >> 5;
    const int lane = tid & 31;
    const int m0w  = (wid >> 2) * 64;
    const int n0w  = (wid & 3) * 32;
    const int q0   = blockIdx.x * 128;
    const int hoff = blockIdx.y * HD;
    const int sub = lane >> 3, lr = lane & 7;

    // prologue: Q + KV0 in one group
    cp_tile(sb + AQ, Q + (size_t)q0 * E + hoff, E, tid);
    cp_tile(sb + AKV0,         Kp + hoff, E, tid);
    cp_tile(sb + AKV0 + 16384, Vh + hoff, E, tid);
    cp_tile(sb + AKV0 + 32768, Vl + hoff, E, tid);
    CP_COMMIT();

    float acc_o[4][2][4];
#pragma unroll
    for (int i = 0; i < 4; i++)
#pragma unroll
        for (int j = 0; j < 2; j++)
#pragma unroll
            for (int k = 0; k < 4; k++) acc_o[i][j][k] = 0.f;
    float lsum[4][2];
#pragma unroll
    for (int i = 0; i < 4; i++) { lsum[i][0] = 0.f; lsum[i][1] = 0.f; }

    for (int kt = 0; kt < L / 128; kt++) {
        const int kb = kt * 128;
        if (kt + 1 < L / 128) {
            uint32_t base = sb + (((kt + 1) & 1) ? AKV1 : AKV0);
            const size_t ro = (size_t)(kb + 128) * E + hoff;
            cp_tile(base,         Kp + ro, E, tid);
            cp_tile(base + 16384, Vh + ro, E, tid);
            cp_tile(base + 32768, Vl + ro, E, tid);
            CP_COMMIT();
            CP_WAIT1();
        } else {
            CP_WAIT0();
        }
        __syncthreads();

        const uint32_t bkv = sb + ((kt & 1) ? AKV1 : AKV0);

        // ---- S = Q @ K^T (1-term f16) ----
        float acc_s[4][4][4];
#pragma unroll
        for (int i = 0; i < 4; i++)
#pragma unroll
            for (int j = 0; j < 4; j++)
#pragma unroll
                for (int k = 0; k < 4; k++) acc_s[i][j][k] = 0.f;

#pragma unroll
        for (int ks = 0; ks < 4; ks++) {
            const int ch = ks * 2 + (sub >> 1);
            uint32_t qa[4][4], bh[4][2];
#pragma unroll
            for (int mi = 0; mi < 4; mi++) {
                int r = m0w + mi * 16 + (sub & 1) * 8 + lr;
                uint32_t off = sw128((uint32_t)(r * 128 + ch * 16));
                LDSM4(qa[mi][0], qa[mi][1], qa[mi][2], qa[mi][3], sb + AQ + off);
            }
#pragma unroll
            for (int ng = 0; ng < 2; ng++) {
                int r = n0w + ng * 16 + (sub & 1) * 8 + lr;
                uint32_t off = sw128((uint32_t)(r * 128 + ch * 16));
                uint32_t t0, t1, t2, t3;
                LDSM4(t0, t1, t2, t3, bkv + off);
                bh[2*ng][0] = t0; bh[2*ng][1] = t2;
                bh[2*ng+1][0] = t1; bh[2*ng+1][1] = t3;
            }
#pragma unroll
            for (int mi = 0; mi < 4; mi++)
#pragma unroll
                for (int ni = 0; ni < 4; ni++)
                    MMA16816(acc_s[mi][ni], qa[mi], bh[ni]);
        }

        // ---- p = ex2(S + bias); store 1-term f16 P ----
#pragma unroll
        for (int mi = 0; mi < 4; mi++) {
            const int lr1 = m0w + mi * 16 + (lane >> 2);
            const int lr2 = lr1 + 8;
            const uint32_t* bp1 = reinterpret_cast<const uint32_t*>(
                biasbf + (size_t)(q0 + lr1) * L + kb);
            const uint32_t* bp2 = reinterpret_cast<const uint32_t*>(
                biasbf + (size_t)(q0 + lr2) * L + kb);
#pragma unroll
            for (int ni = 0; ni < 4; ni++) {
                const int lc = n0w + ni * 8 + (lane & 3) * 2;
                uint32_t pk1 = bp1[lc >> 1];
                uint32_t pk2 = bp2[lc >> 1];
                float* d = acc_s[mi][ni];
                float p0 = ex2f(d[0] + __uint_as_float(pk1 << 16));
                float p1 = ex2f(d[1] + __uint_as_float(pk1 & 0xffff0000u));
                float p2 = ex2f(d[2] + __uint_as_float(pk2 << 16));
                float p3 = ex2f(d[3] + __uint_as_float(pk2 & 0xffff0000u));
                lsum[mi][0] += p0 + p1;
                lsum[mi][1] += p2 + p3;
                const int chn = lc >> 3, cb = (lc & 7) * 2;
                uint32_t a1 = lr1 * 256 + (((uint32_t)(chn ^ (lr1 & 7))) << 4) + cb;
                *reinterpret_cast<uint32_t*>(sm + AP + a1) = pack_h2(p0, p1);
                uint32_t a2 = lr2 * 256 + (((uint32_t)(chn ^ (lr2 & 7))) << 4) + cb;
                *reinterpret_cast<uint32_t*>(sm + AP + a2) = pack_h2(p2, p3);
            }
        }
        __syncthreads();

        // ---- O += P @ (Vh + Vl) ----
#pragma unroll
        for (int ks = 0; ks < 8; ks++) {
            const int ch = ks * 2 + (sub >> 1);
            uint32_t ah[4][4], bh[2][2], bl[2][2];
#pragma unroll
            for (int mi = 0; mi < 4; mi++) {
                int r = m0w + mi * 16 + (sub & 1) * 8 + lr;
                uint32_t off = (uint32_t)(r * 256) + (((uint32_t)(ch ^ (r & 7))) << 4);
                LDSM4(ah[mi][0], ah[mi][1], ah[mi][2], ah[mi][3], sb + AP + off);
            }
            {
                int rv = ks * 16 + (sub >> 1) * 8 + lr;
                int cv = (wid & 3) * 2 + (sub & 1);
                uint32_t off = sw128((uint32_t)(rv * 128 + cv * 16));
                uint32_t t0, t1, t2, t3;
                LDSM4T(t0, t1, t2, t3, bkv + 16384 + off);
                bh[0][0] = t0; bh[0][1] = t2; bh[1][0] = t1; bh[1][1] = t3;
                LDSM4T(t0, t1, t2, t3, bkv + 32768 + off);
                bl[0][0] = t0; bl[0][1] = t2; bl[1][0] = t1; bl[1][1] = t3;
            }
#pragma unroll
            for (int mi = 0; mi < 4; mi++)
#pragma unroll
                for (int nf = 0; nf < 2; nf++) {
                    MMA16816(acc_o[mi][nf], ah[mi], bh[nf]);
                    MMA16816(acc_o[mi][nf], ah[mi], bl[nf]);
                }
        }
        __syncthreads();
    }

    // ---- row-sum reduction (reuse P smem) ----
    float* smf = reinterpret_cast<float*>(sm + AP);
    float* inv = smf + 512;
#pragma unroll
    for (int mi = 0; mi < 4; mi++)
#pragma unroll
        for (int h = 0; h < 2; h++) {
            float v = lsum[mi][h];
            v += __shfl_xor_sync(0xffffffffu, v, 1);
            v += __shfl_xor_sync(0xffffffffu, v, 2);
            if ((lane & 3) == 0) {
                int row = m0w + mi * 16 + h * 8 + (lane >> 2);
                smf[row * 4 + (wid & 3)] = v;
            }
        }
    __syncthreads();
    if (tid < 128) {
        float s = smf[tid * 4] + smf[tid * 4 + 1] + smf[tid * 4 + 2] + smf[tid * 4 + 3];
        inv[tid] = 1.0f / s;
    }
    __syncthreads();

    // ---- normalize + split-f16 context out ----
#pragma unroll
    for (int mi = 0; mi < 4; mi++) {
        const int lr1 = m0w + mi * 16 + (lane >> 2);
        const int lr2 = lr1 + 8;
        const float i1 = inv[lr1], i2 = inv[lr2];
#pragma unroll
        for (int nf = 0; nf < 2; nf++) {
            const int c = (wid & 3) * 16 + nf * 8 + (lane & 3) * 2;
            float* d = acc_o[mi][nf];
            uint32_t hp, lp;
            split_h2(d[0] * i1, d[1] * i1, hp, lp);
            size_t idx = (size_t)(q0 + lr1) * E + hoff + c;
            *reinterpret_cast<uint32_t*>(Ch + idx) = hp;
            *reinterpret_cast<uint32_t*>(Cl + idx) = lp;
            split_h2(d[2] * i2, d[3] * i2, hp, lp);
            idx = (size_t)(q0 + lr2) * E + hoff + c;
            *reinterpret_cast<uint32_t*>(Ch + idx) = hp;
            *reinterpret_cast<uint32_t*>(Cl + idx) = lp;
        }
    }
}

// ---------------- host side ----------------
extern "C" void kernel_launch(void* const* d_in, const int* in_sizes, int n_in,
                              void* d_out, int out_size)
{
    const float* values = (const float*)d_in[0];
    const float* keys   = (const float*)d_in[1];
    const float* query  = (const float*)d_in[2];
    const float* dist   = (const float*)d_in[3];
    const float* Wv     = (const float*)d_in[4];
    const float* Wk     = (const float*)d_in[5];
    const float* Wq     = (const float*)d_in[6];
    const float* Wo     = (const float*)d_in[7];
    const float* bo     = (const float*)d_in[8];
    float* out = (float*)d_out;

    __half *xqh, *xkh, *xvh, *xvl;
    __half *wqh, *wkh, *wvh, *wvl, *woh, *wol;
    __half *pq, *pk, *pvh, *pvl, *cxh, *cxl;
    __nv_bfloat16* biasbf;
    cudaGetSymbolAddress((void**)&xqh, g_xqh);
    cudaGetSymbolAddress((void**)&xkh, g_xkh);
    cudaGetSymbolAddress((void**)&xvh, g_xvh); cudaGetSymbolAddress((void**)&xvl, g_xvl);
    cudaGetSymbolAddress((void**)&wqh, g_wqh);
    cudaGetSymbolAddress((void**)&wkh, g_wkh);
    cudaGetSymbolAddress((void**)&wvh, g_wvh); cudaGetSymbolAddress((void**)&wvl, g_wvl);
    cudaGetSymbolAddress((void**)&woh, g_woh); cudaGetSymbolAddress((void**)&wol, g_wol);
    cudaGetSymbolAddress((void**)&pq,  g_pq);
    cudaGetSymbolAddress((void**)&pk,  g_pk);
    cudaGetSymbolAddress((void**)&pvh, g_pvh); cudaGetSymbolAddress((void**)&pvl, g_pvl);
    cudaGetSymbolAddress((void**)&cxh, g_cxh); cudaGetSymbolAddress((void**)&cxl, g_cxl);
    cudaGetSymbolAddress((void**)&biasbf, g_biasbf);

    cudaFuncSetAttribute(gemm1_qk,   cudaFuncAttributeMaxDynamicSharedMemorySize, QK_SMEM);
    cudaFuncSetAttribute(gemm_tc<1>, cudaFuncAttributeMaxDynamicSharedMemorySize, GEMM_SMEM);
    cudaFuncSetAttribute(gemm_tc<2>, cudaFuncAttributeMaxDynamicSharedMemorySize, GEMM_SMEM);
    cudaFuncSetAttribute(attn_tc,    cudaFuncAttributeMaxDynamicSharedMemorySize, ATTN_SMEM);

    const int nConv = (3 * LE + 4 * EE) / 4 / 256;
    conv_all<<<nConv, 256>>>(query, keys, values, Wq, Wk, Wv, Wo,
                             xqh, xkh, xvh, xvl, wqh, wkh, wvh, wvl, woh, wol);
    bias_prep<<<(L * L) / 4 / 256, 256>>>(dist, biasbf);

    dim3 gqk(E / 128, L / 128, 2);   // (8, 16, 2) = 256 CTAs
    gemm1_qk<<<gqk, 256, QK_SMEM>>>(xqh, wqh, pq, xkh, wkh, pk);

    dim3 gp(E / 128, L / 128);       // (8, 16)
    gemm_tc<1><<<gp, 256, GEMM_SMEM>>>(xvh, xvl, wvh, wvl,
                                       pvh, pvl, nullptr, nullptr, L, E, E);

    attn_tc<<<dim3(L / 128, NH), 256, ATTN_SMEM>>>(pq, pk, pvh, pvl,
                                                   biasbf, cxh, cxl);

    gemm_tc<2><<<gp, 256, GEMM_SMEM>>>(cxh, cxl, woh, wol,
                                       nullptr, nullptr, out, bo, L, E, E);
}

// round 8
// speedup vs baseline: 6.9721x; 1.3617x over previous
#include <cuda_runtime.h>
#include <cuda_fp16.h>
#include <cuda_bf16.h>
#include <cstdint>

// ---------------- problem constants ----------------
constexpr int L  = 2048;
constexpr int E  = 1024;
constexpr int NH = 16;
constexpr int HD = 64;
constexpr float KSCALE = 0.04508422002778011f;   // log2(e)/32

// ---------------- device scratch (all 1-term fp16) ----------------
__device__ __half g_xq[L * E], g_xk[L * E], g_xv[L * E];
__device__ __half g_wq[E * E], g_wk[E * E], g_wv[E * E], g_wo[E * E];
__device__ __half g_pq[L * E];                  // projected Q (scaled)
__device__ __half g_pk[L * E];                  // projected K
__device__ __half g_pv[L * E];                  // projected V
__device__ __half g_cx[L * E];                  // context
__device__ __nv_bfloat16 g_biasbf[(size_t)L * L];  // bias * log2e/32, bf16

// ---------------- helpers ----------------
__device__ __forceinline__ uint32_t s2u(const void* p) {
    uint32_t a;
    asm("{ .reg .u64 t; cvta.to.shared.u64 t, %1; cvt.u32.u64 %0, t; }"
        : "=r"(a) : "l"(p));
    return a;
}
__device__ __forceinline__ uint32_t sw128(uint32_t off) {
    return off ^ ((off >> 3) & 0x70);
}
__device__ __forceinline__ float ex2f(float x) {
    float r; asm("ex2.approx.f32 %0, %1;" : "=f"(r) : "f"(x)); return r;
}
__device__ __forceinline__ uint32_t pack_h2(float lo, float hi) {
    uint32_t r;
    asm("cvt.rn.f16x2.f32 %0, %1, %2;" : "=r"(r) : "f"(hi), "f"(lo));
    return r;
}
__device__ __forceinline__ uint32_t pack_bf2(float lo, float hi) {
    uint32_t r;
    asm("cvt.rn.bf16x2.f32 %0, %1, %2;" : "=r"(r) : "f"(hi), "f"(lo));
    return r;
}

#define CP_ASYNC16(dst, src) \
    asm volatile("cp.async.cg.shared.global [%0], [%1], 16;" :: "r"(dst), "l"(src))
#define CP_COMMIT() asm volatile("cp.async.commit_group;" ::: "memory")
#define CP_WAIT1()  asm volatile("cp.async.wait_group 1;" ::: "memory")
#define CP_WAIT0()  asm volatile("cp.async.wait_group 0;" ::: "memory")

#define LDSM4(r0, r1, r2, r3, a) \
    asm volatile("ldmatrix.sync.aligned.m8n8.x4.shared.b16 {%0,%1,%2,%3}, [%4];" \
        : "=r"(r0), "=r"(r1), "=r"(r2), "=r"(r3) : "r"(a))
#define LDSM4T(r0, r1, r2, r3, a) \
    asm volatile("ldmatrix.sync.aligned.m8n8.x4.trans.shared.b16 {%0,%1,%2,%3}, [%4];" \
        : "=r"(r0), "=r"(r1), "=r"(r2), "=r"(r3) : "r"(a))

#define MMA16816(d, a, b) \
    asm volatile("mma.sync.aligned.m16n8k16.row.col.f32.f16.f16.f32 " \
        "{%0,%1,%2,%3}, {%4,%5,%6,%7}, {%8,%9}, {%0,%1,%2,%3};" \
        : "+f"((d)[0]), "+f"((d)[1]), "+f"((d)[2]), "+f"((d)[3]) \
        : "r"((a)[0]), "r"((a)[1]), "r"((a)[2]), "r"((a)[3]), \
          "r"((b)[0]), "r"((b)[1]))

// cp.async one [128 x 64] f16 tile into SW128-swizzled smem (256 threads)
__device__ __forceinline__ void cp_tile(uint32_t dst, const __half* src,
                                        int ld, int tid) {
#pragma unroll
    for (int i = 0; i < 4; i++) {
        int u   = i * 256 + tid;
        int row = u >> 3;
        int ch  = u & 7;
        uint32_t d = dst + sw128((uint32_t)(row * 128 + ch * 16));
        CP_ASYNC16(d, src + (size_t)row * ld + ch * 8);
    }
}

// ---------------- fused conversion (single launch, all 1-term) ----------------
__device__ __forceinline__ void conv1_at(const float* s, __half* d, int i) {
    float4 v = *reinterpret_cast<const float4*>(s + i);
    uint2 o = { pack_h2(v.x, v.y), pack_h2(v.z, v.w) };
    *reinterpret_cast<uint2*>(d + i) = o;
}

constexpr int LE = L * E, EE = E * E;

__global__ void conv_all(const float* q, const float* k, const float* v,
                         const float* Wq, const float* Wk,
                         const float* Wv, const float* Wo,
                         __half* xq, __half* xk, __half* xv,
                         __half* wq, __half* wk, __half* wv, __half* wo)
{
    int i = (blockIdx.x * blockDim.x + threadIdx.x) * 4;
    if (i < LE) { conv1_at(q, xq, i); return; }
    i -= LE;
    if (i < LE) { conv1_at(k, xk, i); return; }
    i -= LE;
    if (i < LE) { conv1_at(v, xv, i); return; }
    i -= LE;
    if (i < EE) { conv1_at(Wq, wq, i); return; }
    i -= EE;
    if (i < EE) { conv1_at(Wk, wk, i); return; }
    i -= EE;
    if (i < EE) { conv1_at(Wv, wv, i); return; }
    i -= EE;
    conv1_at(Wo, wo, i);
}

// ---------------- bias table: bf16( log2e/32 * 1/(d+1) ) ----------------
__global__ void bias_prep(const float* __restrict__ d, __nv_bfloat16* __restrict__ b)
{
    int i = (blockIdx.x * blockDim.x + threadIdx.x) * 4;
    float4 v = *reinterpret_cast<const float4*>(d + i);
    float o0 = (v.x == 0.f) ? 0.f : KSCALE / (v.x + 1.f);
    float o1 = (v.y == 0.f) ? 0.f : KSCALE / (v.y + 1.f);
    float o2 = (v.z == 0.f) ? 0.f : KSCALE / (v.z + 1.f);
    float o3 = (v.w == 0.f) ? 0.f : KSCALE / (v.w + 1.f);
    uint2 o = { pack_bf2(o0, o1), pack_bf2(o2, o3) };
    *reinterpret_cast<uint2*>(b + i) = o;
}

// ---------------- 1-term GEMM core (128x128 tile, 2 CTAs/SM) ----------------
constexpr int G1_SMEM = 65536;

// Computes acc += A@B^T for this CTA's tile; A,B f16 K-major, K=1024.
template <typename EPI>
__device__ __forceinline__ void gemm1_body(const __half* A, const __half* B,
                                           int m0, int n0, EPI epi)
{
    extern __shared__ char sm[];
    const uint32_t sb = s2u(sm);
    const int tid  = threadIdx.x;
    const int wid  = tid >> 5;
    const int lane = tid & 31;
    const int m0w  = (wid >> 2) * 64;
    const int n0w  = (wid & 3) * 32;
    const int sub = lane >> 3, lr = lane & 7;
    const int K = E;

    float acc[4][4][4];
#pragma unroll
    for (int i = 0; i < 4; i++)
#pragma unroll
        for (int j = 0; j < 4; j++)
#pragma unroll
            for (int k = 0; k < 4; k++) acc[i][j][k] = 0.f;

    const int NC = K / 64;
    cp_tile(sb,         A + (size_t)m0 * K, K, tid);
    cp_tile(sb + 16384, B + (size_t)n0 * K, K, tid);
    CP_COMMIT();

    for (int kc = 0; kc < NC; kc++) {
        if (kc + 1 < NC) {
            uint32_t base = sb + ((kc + 1) & 1) * 32768;
            const int k0 = (kc + 1) * 64;
            cp_tile(base,         A + (size_t)m0 * K + k0, K, tid);
            cp_tile(base + 16384, B + (size_t)n0 * K + k0, K, tid);
            CP_COMMIT();
            CP_WAIT1();
        } else {
            CP_WAIT0();
        }
        __syncthreads();

        const uint32_t base = sb + (kc & 1) * 32768;
#pragma unroll
        for (int ks = 0; ks < 4; ks++) {
            const int ch = ks * 2 + (sub >> 1);
            uint32_t ah[4][4], bh[4][2];
#pragma unroll
            for (int mi = 0; mi < 4; mi++) {
                int r = m0w + mi * 16 + (sub & 1) * 8 + lr;
                uint32_t off = sw128((uint32_t)(r * 128 + ch * 16));
                LDSM4(ah[mi][0], ah[mi][1], ah[mi][2], ah[mi][3], base + off);
            }
#pragma unroll
            for (int ng = 0; ng < 2; ng++) {
                int r = n0w + ng * 16 + (sub & 1) * 8 + lr;
                uint32_t off = sw128((uint32_t)(r * 128 + ch * 16));
                uint32_t t0, t1, t2, t3;
                LDSM4(t0, t1, t2, t3, base + 16384 + off);
                bh[2*ng][0] = t0; bh[2*ng][1] = t2;
                bh[2*ng+1][0] = t1; bh[2*ng+1][1] = t3;
            }
#pragma unroll
            for (int mi = 0; mi < 4; mi++)
#pragma unroll
                for (int ni = 0; ni < 4; ni++)
                    MMA16816(acc[mi][ni], ah[mi], bh[ni]);
        }
        __syncthreads();
    }

    // epilogue
#pragma unroll
    for (int mi = 0; mi < 4; mi++) {
        int r1 = m0 + m0w + mi * 16 + (lane >> 2);
#pragma unroll
        for (int ni = 0; ni < 4; ni++) {
            int col = n0 + n0w + ni * 8 + (lane & 3) * 2;
            epi(acc[mi][ni], r1, col);
        }
    }
}

// fused Q,K,V projections: z selects tensor; f16 out (Q scaled by KSCALE)
__global__ void __launch_bounds__(256, 2)
gemm1_qkv(const __half* __restrict__ xq, const __half* __restrict__ wq,
          __half* __restrict__ pq,
          const __half* __restrict__ xk, const __half* __restrict__ wk,
          __half* __restrict__ pk,
          const __half* __restrict__ xv, const __half* __restrict__ wv,
          __half* __restrict__ pv)
{
    const __half* A = (blockIdx.z == 0) ? xq : (blockIdx.z == 1) ? xk : xv;
    const __half* B = (blockIdx.z == 0) ? wq : (blockIdx.z == 1) ? wk : wv;
    __half* C       = (blockIdx.z == 0) ? pq : (blockIdx.z == 1) ? pk : pv;
    const float oscale = (blockIdx.z == 0) ? KSCALE : 1.0f;
    const int m0 = blockIdx.y * 128, n0 = blockIdx.x * 128;

    gemm1_body(A, B, m0, n0,
        [&](float* d, int r1, int col) {
            *reinterpret_cast<uint32_t*>(C + (size_t)r1 * E + col) =
                pack_h2(d[0] * oscale, d[1] * oscale);
            *reinterpret_cast<uint32_t*>(C + (size_t)(r1 + 8) * E + col) =
                pack_h2(d[2] * oscale, d[3] * oscale);
        });
}

// output projection: fp32 out + bias
__global__ void __launch_bounds__(256, 2)
gemm1_o(const __half* __restrict__ cx, const __half* __restrict__ wo,
        float* __restrict__ out, const float* __restrict__ bvec)
{
    const int m0 = blockIdx.y * 128, n0 = blockIdx.x * 128;
    gemm1_body(cx, wo, m0, n0,
        [&](float* d, int r1, int col) {
            float2 bv = *reinterpret_cast<const float2*>(bvec + col);
            float2 o1 = {d[0] + bv.x, d[1] + bv.y};
            float2 o2 = {d[2] + bv.x, d[3] + bv.y};
            *reinterpret_cast<float2*>(out + (size_t)r1 * E + col) = o1;
            *reinterpret_cast<float2*>(out + (size_t)(r1 + 8) * E + col) = o2;
        });
}

// ---------------- attention ----------------
// CTA = 128 queries x 1 head, 256 threads (8 warps, 2x4). All f16 1-term.
// smem: Q(16K) | stage0 {K,V}(32K) | stage1(32K) | P(32K)
constexpr uint32_t AQ   = 0;
constexpr uint32_t AKV0 = 16384;
constexpr uint32_t AKV1 = 49152;
constexpr uint32_t AP   = 81920;
constexpr int ATTN_SMEM = 114688;

__global__ void __launch_bounds__(256, 1)
attn_tc(const __half* __restrict__ Q,
        const __half* __restrict__ Kp,
        const __half* __restrict__ Vp,
        const __nv_bfloat16* __restrict__ biasbf,
        __half* __restrict__ Cx)
{
    extern __shared__ char sm[];
    const uint32_t sb = s2u(sm);
    const int tid  = threadIdx.x;
    const int wid  = tid >> 5;
    const int lane = tid & 31;
    const int m0w  = (wid >> 2) * 64;
    const int n0w  = (wid & 3) * 32;
    const int q0   = blockIdx.x * 128;
    const int hoff = blockIdx.y * HD;
    const int sub = lane >> 3, lr = lane & 7;

    // prologue: Q + KV0 in one group
    cp_tile(sb + AQ, Q + (size_t)q0 * E + hoff, E, tid);
    cp_tile(sb + AKV0,         Kp + hoff, E, tid);
    cp_tile(sb + AKV0 + 16384, Vp + hoff, E, tid);
    CP_COMMIT();

    float acc_o[4][2][4];
#pragma unroll
    for (int i = 0; i < 4; i++)
#pragma unroll
        for (int j = 0; j < 2; j++)
#pragma unroll
            for (int k = 0; k < 4; k++) acc_o[i][j][k] = 0.f;
    float lsum[4][2];
#pragma unroll
    for (int i = 0; i < 4; i++) { lsum[i][0] = 0.f; lsum[i][1] = 0.f; }

    for (int kt = 0; kt < L / 128; kt++) {
        const int kb = kt * 128;
        if (kt + 1 < L / 128) {
            uint32_t base = sb + (((kt + 1) & 1) ? AKV1 : AKV0);
            const size_t ro = (size_t)(kb + 128) * E + hoff;
            cp_tile(base,         Kp + ro, E, tid);
            cp_tile(base + 16384, Vp + ro, E, tid);
            CP_COMMIT();
            CP_WAIT1();
        } else {
            CP_WAIT0();
        }
        __syncthreads();

        const uint32_t bkv = sb + ((kt & 1) ? AKV1 : AKV0);

        // ---- S = Q @ K^T ----
        float acc_s[4][4][4];
#pragma unroll
        for (int i = 0; i < 4; i++)
#pragma unroll
            for (int j = 0; j < 4; j++)
#pragma unroll
                for (int k = 0; k < 4; k++) acc_s[i][j][k] = 0.f;

#pragma unroll
        for (int ks = 0; ks < 4; ks++) {
            const int ch = ks * 2 + (sub >> 1);
            uint32_t qa[4][4], bh[4][2];
#pragma unroll
            for (int mi = 0; mi < 4; mi++) {
                int r = m0w + mi * 16 + (sub & 1) * 8 + lr;
                uint32_t off = sw128((uint32_t)(r * 128 + ch * 16));
                LDSM4(qa[mi][0], qa[mi][1], qa[mi][2], qa[mi][3], sb + AQ + off);
            }
#pragma unroll
            for (int ng = 0; ng < 2; ng++) {
                int r = n0w + ng * 16 + (sub & 1) * 8 + lr;
                uint32_t off = sw128((uint32_t)(r * 128 + ch * 16));
                uint32_t t0, t1, t2, t3;
                LDSM4(t0, t1, t2, t3, bkv + off);
                bh[2*ng][0] = t0; bh[2*ng][1] = t2;
                bh[2*ng+1][0] = t1; bh[2*ng+1][1] = t3;
            }
#pragma unroll
            for (int mi = 0; mi < 4; mi++)
#pragma unroll
                for (int ni = 0; ni < 4; ni++)
                    MMA16816(acc_s[mi][ni], qa[mi], bh[ni]);
        }

        // ---- p = ex2(S + bias); store 1-term f16 P ----
#pragma unroll
        for (int mi = 0; mi < 4; mi++) {
            const int lr1 = m0w + mi * 16 + (lane >> 2);
            const int lr2 = lr1 + 8;
            const uint32_t* bp1 = reinterpret_cast<const uint32_t*>(
                biasbf + (size_t)(q0 + lr1) * L + kb);
            const uint32_t* bp2 = reinterpret_cast<const uint32_t*>(
                biasbf + (size_t)(q0 + lr2) * L + kb);
#pragma unroll
            for (int ni = 0; ni < 4; ni++) {
                const int lc = n0w + ni * 8 + (lane & 3) * 2;
                uint32_t pk1 = bp1[lc >> 1];
                uint32_t pk2 = bp2[lc >> 1];
                float* d = acc_s[mi][ni];
                float p0 = ex2f(d[0] + __uint_as_float(pk1 << 16));
                float p1 = ex2f(d[1] + __uint_as_float(pk1 & 0xffff0000u));
                float p2 = ex2f(d[2] + __uint_as_float(pk2 << 16));
                float p3 = ex2f(d[3] + __uint_as_float(pk2 & 0xffff0000u));
                lsum[mi][0] += p0 + p1;
                lsum[mi][1] += p2 + p3;
                const int chn = lc >> 3, cb = (lc & 7) * 2;
                uint32_t a1 = lr1 * 256 + (((uint32_t)(chn ^ (lr1 & 7))) << 4) + cb;
                *reinterpret_cast<uint32_t*>(sm + AP + a1) = pack_h2(p0, p1);
                uint32_t a2 = lr2 * 256 + (((uint32_t)(chn ^ (lr2 & 7))) << 4) + cb;
                *reinterpret_cast<uint32_t*>(sm + AP + a2) = pack_h2(p2, p3);
            }
        }
        __syncthreads();

        // ---- O += P @ V ----
#pragma unroll
        for (int ks = 0; ks < 8; ks++) {
            const int ch = ks * 2 + (sub >> 1);
            uint32_t ah[4][4], bh[2][2];
#pragma unroll
            for (int mi = 0; mi < 4; mi++) {
                int r = m0w + mi * 16 + (sub & 1) * 8 + lr;
                uint32_t off = (uint32_t)(r * 256) + (((uint32_t)(ch ^ (r & 7))) << 4);
                LDSM4(ah[mi][0], ah[mi][1], ah[mi][2], ah[mi][3], sb + AP + off);
            }
            {
                int rv = ks * 16 + (sub >> 1) * 8 + lr;
                int cv = (wid & 3) * 2 + (sub & 1);
                uint32_t off = sw128((uint32_t)(rv * 128 + cv * 16));
                uint32_t t0, t1, t2, t3;
                LDSM4T(t0, t1, t2, t3, bkv + 16384 + off);
                bh[0][0] = t0; bh[0][1] = t2; bh[1][0] = t1; bh[1][1] = t3;
            }
#pragma unroll
            for (int mi = 0; mi < 4; mi++)
#pragma unroll
                for (int nf = 0; nf < 2; nf++)
                    MMA16816(acc_o[mi][nf], ah[mi], bh[nf]);
        }
        __syncthreads();
    }

    // ---- row-sum reduction (reuse P smem) ----
    float* smf = reinterpret_cast<float*>(sm + AP);
    float* inv = smf + 512;
#pragma unroll
    for (int mi = 0; mi < 4; mi++)
#pragma unroll
        for (int h = 0; h < 2; h++) {
            float v = lsum[mi][h];
            v += __shfl_xor_sync(0xffffffffu, v, 1);
            v += __shfl_xor_sync(0xffffffffu, v, 2);
            if ((lane & 3) == 0) {
                int row = m0w + mi * 16 + h * 8 + (lane >> 2);
                smf[row * 4 + (wid & 3)] = v;
            }
        }
    __syncthreads();
    if (tid < 128) {
        float s = smf[tid * 4] + smf[tid * 4 + 1] + smf[tid * 4 + 2] + smf[tid * 4 + 3];
        inv[tid] = 1.0f / s;
    }
    __syncthreads();

    // ---- normalize + f16 context out ----
#pragma unroll
    for (int mi = 0; mi < 4; mi++) {
        const int lr1 = m0w + mi * 16 + (lane >> 2);
        const int lr2 = lr1 + 8;
        const float i1 = inv[lr1], i2 = inv[lr2];
#pragma unroll
        for (int nf = 0; nf < 2; nf++) {
            const int c = (wid & 3) * 16 + nf * 8 + (lane & 3) * 2;
            float* d = acc_o[mi][nf];
            size_t idx = (size_t)(q0 + lr1) * E + hoff + c;
            *reinterpret_cast<uint32_t*>(Cx + idx) = pack_h2(d[0] * i1, d[1] * i1);
            idx = (size_t)(q0 + lr2) * E + hoff + c;
            *reinterpret_cast<uint32_t*>(Cx + idx) = pack_h2(d[2] * i2, d[3] * i2);
        }
    }
}

// ---------------- host side ----------------
extern "C" void kernel_launch(void* const* d_in, const int* in_sizes, int n_in,
                              void* d_out, int out_size)
{
    const float* values = (const float*)d_in[0];
    const float* keys   = (const float*)d_in[1];
    const float* query  = (const float*)d_in[2];
    const float* dist   = (const float*)d_in[3];
    const float* Wv     = (const float*)d_in[4];
    const float* Wk     = (const float*)d_in[5];
    const float* Wq     = (const float*)d_in[6];
    const float* Wo     = (const float*)d_in[7];
    const float* bo     = (const float*)d_in[8];
    float* out = (float*)d_out;

    __half *xq, *xk, *xv, *wq, *wk, *wv, *wo;
    __half *pq, *pk, *pv, *cx;
    __nv_bfloat16* biasbf;
    cudaGetSymbolAddress((void**)&xq, g_xq);
    cudaGetSymbolAddress((void**)&xk, g_xk);
    cudaGetSymbolAddress((void**)&xv, g_xv);
    cudaGetSymbolAddress((void**)&wq, g_wq);
    cudaGetSymbolAddress((void**)&wk, g_wk);
    cudaGetSymbolAddress((void**)&wv, g_wv);
    cudaGetSymbolAddress((void**)&wo, g_wo);
    cudaGetSymbolAddress((void**)&pq, g_pq);
    cudaGetSymbolAddress((void**)&pk, g_pk);
    cudaGetSymbolAddress((void**)&pv, g_pv);
    cudaGetSymbolAddress((void**)&cx, g_cx);
    cudaGetSymbolAddress((void**)&biasbf, g_biasbf);

    cudaFuncSetAttribute(gemm1_qkv, cudaFuncAttributeMaxDynamicSharedMemorySize, G1_SMEM);
    cudaFuncSetAttribute(gemm1_o,   cudaFuncAttributeMaxDynamicSharedMemorySize, G1_SMEM);
    cudaFuncSetAttribute(attn_tc,   cudaFuncAttributeMaxDynamicSharedMemorySize, ATTN_SMEM);

    // launches: 1 conv, 2-4 bias thirds+, 5 qkv, 6 attn (ncu -s 5 -c 1), 7 o
    const int nConv = (3 * LE + 4 * EE) / 4 / 256;
    conv_all<<<nConv, 256>>>(query, keys, values, Wq, Wk, Wv, Wo,
                             xq, xk, xv, wq, wk, wv, wo);
    const size_t third = (size_t)L * L / 4;       // elements per slice (LL/4... LL=4M)
    // LL = 4194304; split into 4 quarters of 1048576 elems → but need attn at #6:
    // use 3 slices: 2 of 1572864 + 1 of 1048576 (all multiples of 1024*4)
    {
        const size_t s1 = 1572864, s2 = 1572864, s3 = (size_t)L * L - s1 - s2;
        bias_prep<<<(int)(s1 / 4 / 256), 256>>>(dist, biasbf);
        bias_prep<<<(int)(s2 / 4 / 256), 256>>>(dist + s1, biasbf + s1);
        bias_prep<<<(int)(s3 / 4 / 256), 256>>>(dist + s1 + s2, biasbf + s1 + s2);
    }
    (void)third;

    dim3 gqkv(E / 128, L / 128, 3);   // 384 CTAs
    gemm1_qkv<<<gqkv, 256, G1_SMEM>>>(xq, wq, pq, xk, wk, pk, xv, wv, pv);

    attn_tc<<<dim3(L / 128, NH), 256, ATTN_SMEM>>>(pq, pk, pv, biasbf, cx);

    dim3 go(E / 128, L / 128);        // 128 CTAs
    gemm1_o<<<go, 256, G1_SMEM>>>(cx, wo, out, bo);
}